// round 13
// baseline (speedup 1.0000x reference)
#include <cuda_runtime.h>
#include <cuda_fp16.h>
#include <cstdint>
#include <math.h>

// Problem constants
static constexpr int NB   = 4;
static constexpr int C    = 512;
static constexpr int HW   = 16384;
static constexpr int K    = 19;
static constexpr int KC   = 256;
static constexpr int OUTC = 512;
static constexpr int PCH  = 128;    // proxy spatial chunks

// ---------------- scratch (device globals, no allocation) ----------------
__device__ float g_p[NB * K * HW];
__device__ float g_ppart[PCH * NB * C * K];
__device__ float g_proxy[NB * C * K];
__device__ float g_o1[NB * KC * K];
__device__ float g_kk[NB * KC * K];
__device__ float g_val[NB * KC * K];
__device__ __half g_featsh[NB * C * HW];
__device__ __half g_q1h[NB * KC * HW];
__device__ __half g_q2h[NB * KC * HW];
__device__ __half g_ctxh[NB * KC * HW];
__device__ __half g_ctxuph[NB * C * HW];
__device__ __half g_wp1h[KC * C];
__device__ __half g_wp2h[KC * KC];
__device__ __half g_wuh[C * KC];
__device__ __half g_wfh[OUTC * 2 * C];

// ---------------- PTX helpers ----------------
__device__ __forceinline__ void mma_f16(float* d, uint32_t a0, uint32_t a1, uint32_t a2, uint32_t a3,
                                        uint32_t b0, uint32_t b1) {
    asm volatile(
        "mma.sync.aligned.m16n8k16.row.col.f32.f16.f16.f32 "
        "{%0,%1,%2,%3}, {%4,%5,%6,%7}, {%8,%9}, {%0,%1,%2,%3};\n"
        : "+f"(d[0]), "+f"(d[1]), "+f"(d[2]), "+f"(d[3])
        : "r"(a0), "r"(a1), "r"(a2), "r"(a3), "r"(b0), "r"(b1));
}
__device__ __forceinline__ void ldm_x4(uint32_t* r, uint32_t addr) {
    asm volatile("ldmatrix.sync.aligned.m8n8.x4.shared.b16 {%0,%1,%2,%3}, [%4];"
                 : "=r"(r[0]), "=r"(r[1]), "=r"(r[2]), "=r"(r[3]) : "r"(addr));
}
__device__ __forceinline__ void ldm_x4_t(uint32_t* r, uint32_t addr) {
    asm volatile("ldmatrix.sync.aligned.m8n8.x4.trans.shared.b16 {%0,%1,%2,%3}, [%4];"
                 : "=r"(r[0]), "=r"(r[1]), "=r"(r[2]), "=r"(r[3]) : "r"(addr));
}
__device__ __forceinline__ void cp16(uint32_t saddr, const void* g) {
    asm volatile("cp.async.cg.shared.global [%0], [%1], 16;" :: "r"(saddr), "l"(g) : "memory");
}
__device__ __forceinline__ void cp_commit() { asm volatile("cp.async.commit_group;" ::: "memory"); }
template <int N>
__device__ __forceinline__ void cp_wait() { asm volatile("cp.async.wait_group %0;" :: "n"(N) : "memory"); }

// ---------------- 0) fp32 -> fp16 conversions ----------------
__global__ __launch_bounds__(256) void f2h_kernel(const float4* __restrict__ in,
                                                  uint2* __restrict__ out, int n4) {
    int i = blockIdx.x * 256 + threadIdx.x;
    if (i >= n4) return;
    float4 v = in[i];
    __half2 a = __floats2half2_rn(v.x, v.y);
    __half2 b = __floats2half2_rn(v.z, v.w);
    uint2 t; t.x = *(uint32_t*)&a; t.y = *(uint32_t*)&b;
    out[i] = t;
}

struct W4 {
    const float4* in[4];
    uint2* out[4];
    int end[4];
};
__global__ __launch_bounds__(256) void f2h_weights(W4 w) {
    int i = blockIdx.x * 256 + threadIdx.x;
    int r = 0, base = 0;
    if (i >= w.end[3]) return;
    if (i >= w.end[2])      { r = 3; base = w.end[2]; }
    else if (i >= w.end[1]) { r = 2; base = w.end[1]; }
    else if (i >= w.end[0]) { r = 1; base = w.end[0]; }
    int j = i - base;
    float4 v = w.in[r][j];
    __half2 a = __floats2half2_rn(v.x, v.y);
    __half2 b = __floats2half2_rn(v.z, v.w);
    uint2 t; t.x = *(uint32_t*)&a; t.y = *(uint32_t*)&b;
    w.out[r][j] = t;
}

// ---------------- 1) spatial softmax over probs ----------------
__global__ __launch_bounds__(512) void softmax_kernel(const float* __restrict__ probs) {
    const int row = blockIdx.x;
    const float4* x4 = (const float4*)(probs + (size_t)row * HW);
    float4* y4 = (float4*)(g_p + (size_t)row * HW);
    const int tid = threadIdx.x;
    const int lane = tid & 31, wrp = tid >> 5;
    __shared__ float red[16];

    float m = -1e30f;
    for (int i = tid; i < HW / 4; i += 512) {
        float4 v = x4[i];
        m = fmaxf(fmaxf(m, fmaxf(v.x, v.y)), fmaxf(v.z, v.w));
    }
#pragma unroll
    for (int off = 16; off > 0; off >>= 1) m = fmaxf(m, __shfl_xor_sync(~0u, m, off));
    if (lane == 0) red[wrp] = m;
    __syncthreads();
    m = red[lane & 15];
#pragma unroll
    for (int off = 8; off > 0; off >>= 1) m = fmaxf(m, __shfl_xor_sync(~0u, m, off));

    float sum = 0.f;
    for (int i = tid; i < HW / 4; i += 512) {
        float4 v = x4[i];
        v.x = __expf(v.x - m); v.y = __expf(v.y - m);
        v.z = __expf(v.z - m); v.w = __expf(v.w - m);
        y4[i] = v;
        sum += v.x + v.y + v.z + v.w;
    }
#pragma unroll
    for (int off = 16; off > 0; off >>= 1) sum += __shfl_xor_sync(~0u, sum, off);
    __syncthreads();
    if (lane == 0) red[wrp] = sum;
    __syncthreads();
    sum = red[lane & 15];
#pragma unroll
    for (int off = 8; off > 0; off >>= 1) sum += __shfl_xor_sync(~0u, sum, off);
    const float inv = 1.0f / sum;
    for (int i = tid; i < HW / 4; i += 512) {
        float4 v = y4[i];
        v.x *= inv; v.y *= inv; v.z *= inv; v.w *= inv;
        y4[i] = v;
    }
}

// ---------------- 2) proxy pooling: transposed smem tile ----------------
__global__ __launch_bounds__(256) void proxy_partial2() {
    const int ch = blockIdx.x;
    const int n  = blockIdx.y;
    const int tid = threadIdx.x;

    __shared__ __half sf[32][520];
    __shared__ float sp[19][33];

    float acc[2][K];
#pragma unroll
    for (int h = 0; h < 2; h++)
#pragma unroll
        for (int k = 0; k < K; k++) acc[h][k] = 0.f;

    const __half* fb = g_featsh + (size_t)n * C * HW;
    const float* pb = g_p + (size_t)n * K * HW;
    const int c0 = 2 * tid;
    const int sbeg = ch * (HW / PCH), send = sbeg + (HW / PCH);

    for (int s0 = sbeg; s0 < send; s0 += 32) {
        {
            int c = tid;
#pragma unroll
            for (int h = 0; h < 2; h++, c += 256) {
                const __half* gp = fb + (size_t)c * HW + s0;
#pragma unroll
                for (int q = 0; q < 4; q++) {
                    uint4 v = *(const uint4*)(gp + q * 8);
                    const __half* hh = (const __half*)&v;
#pragma unroll
                    for (int j = 0; j < 8; j++) sf[q * 8 + j][c] = hh[j];
                }
            }
        }
        for (int i = tid; i < K * 32; i += 256) {
            int k = i >> 5, s = i & 31;
            sp[k][s] = pb[(size_t)k * HW + s0 + s];
        }
        __syncthreads();
#pragma unroll 2
        for (int s = 0; s < 32; s++) {
            __half2 hv = *(const __half2*)&sf[s][c0];
            float2 f = __half22float2(hv);
#pragma unroll
            for (int k = 0; k < K; k++) {
                float pv = sp[k][s];
                acc[0][k] += f.x * pv;
                acc[1][k] += f.y * pv;
            }
        }
        __syncthreads();
    }

#pragma unroll
    for (int h = 0; h < 2; h++) {
        float* ob = g_ppart + ((size_t)ch * NB + n) * C * K + (size_t)(c0 + h) * K;
#pragma unroll
        for (int k = 0; k < K; k++) ob[k] = acc[h][k];
    }
}

__global__ __launch_bounds__(256) void proxy_reduce() {
    int e = blockIdx.x * 256 + threadIdx.x;
    if (e >= NB * C * K) return;
    float s = 0.f;
#pragma unroll 8
    for (int ch = 0; ch < PCH; ch++) s += g_ppart[(size_t)ch * NB * C * K + e];
    g_proxy[e] = s;
}

// ---------------- 3) tiny conv1x1+BN+ReLU ----------------
__global__ __launch_bounds__(256) void small_cbr2(const float* __restrict__ in,
                                                  const float* __restrict__ wA,
                                                  const float* __restrict__ bA,
                                                  const float* __restrict__ scA,
                                                  const float* __restrict__ shA,
                                                  float* __restrict__ outA,
                                                  const float* __restrict__ wB,
                                                  const float* __restrict__ bB,
                                                  const float* __restrict__ scB,
                                                  const float* __restrict__ shB,
                                                  float* __restrict__ outB,
                                                  int Cin, float fscale) {
    const int n = blockIdx.x;
    const int ob = blockIdx.y;
    const int tid = threadIdx.x;
    const float* w  = blockIdx.z ? wB : wA;
    const float* b  = blockIdx.z ? bB : bA;
    const float* sc = blockIdx.z ? scB : scA;
    const float* sh = blockIdx.z ? shB : shA;
    float* out      = blockIdx.z ? outB : outA;

    extern __shared__ float sin_[];
    const float* ibase = in + (size_t)n * Cin * K;
    for (int i = tid; i < Cin * 20; i += 256) {
        int c = i / 20, k = i - c * 20;
        sin_[i] = (k < K) ? ibase[c * K + k] : 0.f;
    }
    __syncthreads();

    const int o = ob * 32 + (tid >> 3);
    const int part = tid & 7;

    float acc[K];
#pragma unroll
    for (int k = 0; k < K; k++) acc[k] = 0.f;

    const float* wrow = w + (size_t)o * Cin;
    for (int c = part; c < Cin; c += 8) {
        float wv = wrow[c];
        const float* srow = &sin_[c * 20];
#pragma unroll
        for (int k = 0; k < K; k++) acc[k] += wv * srow[k];
    }
#pragma unroll
    for (int off = 4; off > 0; off >>= 1)
#pragma unroll
        for (int k = 0; k < K; k++) acc[k] += __shfl_down_sync(0xffffffffu, acc[k], off, 8);

    if (part == 0) {
        const float bb = b[o], ss = sc[o], tt = sh[o];
        float* obase = out + ((size_t)n * KC + o) * K;
#pragma unroll
        for (int k = 0; k < K; k++) obase[k] = fmaxf((acc[k] + bb) * ss + tt, 0.f) * fscale;
    }
}

// ---------------- 4) fp16 mma CBR GEMM: BM=256, 512 threads, 3-stage cp.async ----------------
static constexpr int BM = 256;
static constexpr int A_PITCH_H = 40;
static constexpr int B_PITCH_H = 136;
static constexpr int A_BYTES = BM * A_PITCH_H * 2;   // 20480
static constexpr int B_BYTES = 32 * B_PITCH_H * 2;   // 8704
static constexpr int NSTAGE = 3;
static constexpr int GEMM_SMEM = NSTAGE * (A_BYTES + B_BYTES) + 3 * BM * 4;  // 90624

__global__ __launch_bounds__(512, 2) void cbr_gemm_mma(const __half* __restrict__ in1,
                                                       const __half* __restrict__ in2,
                                                       const __half* __restrict__ wh,
                                                       const float* __restrict__ bias,
                                                       const float* __restrict__ sc,
                                                       const float* __restrict__ sh,
                                                       void* __restrict__ outp, int out_half,
                                                       int Cin, int split, int Cout) {
    extern __shared__ char smem_c[];
    float* par = (float*)(smem_c + NSTAGE * (A_BYTES + B_BYTES));

    const int tid  = threadIdx.x;
    const int lane = tid & 31;
    const int wid  = tid >> 5;                 // 0..15
    const int n    = blockIdx.z;
    const int s0   = blockIdx.x * 128;
    const int o0   = blockIdx.y * BM;

    const int m0w = (wid & 3) * 64;            // 4 warps along M
    const int n0w = (wid >> 2) * 32;           // 4 warps along N
    const int gid = lane >> 2;
    const int tg  = lane & 3;

    uint32_t smem_u32;
    asm("{ .reg .u64 t; cvta.to.shared.u64 t, %1; cvt.u32.u64 %0, t; }" : "=r"(smem_u32) : "l"(smem_c));
    const uint32_t A_u = smem_u32;
    const uint32_t B_u = smem_u32 + NSTAGE * A_BYTES;

    if (tid < BM) {
        par[tid]           = bias[o0 + tid];
        par[BM + tid]      = sc[o0 + tid];
        par[2 * BM + tid]  = sh[o0 + tid];
    }

    const int T = Cin >> 5;
    const __half* in1n = in1 + (size_t)n * split * HW;
    const __half* in2n = in2 ? (in2 + (size_t)n * (Cin - split) * HW) : nullptr;

    // loader assignments (512 threads)
    const int bkk = tid >> 4, bcq = tid & 15;  // B: 32 rows x 16 chunks, 1 cp16 each
    const int am  = tid >> 1, ac2 = tid & 1;   // A: 256 rows x 4 chunks, 2 cp16 each

    float acc[4][4][4];
#pragma unroll
    for (int mi = 0; mi < 4; mi++)
#pragma unroll
        for (int ni = 0; ni < 4; ni++)
#pragma unroll
            for (int r = 0; r < 4; r++) acc[mi][ni][r] = 0.f;

    auto load_tile = [&](int kt) {
        const int st = kt % NSTAGE;
        const uint32_t Ab = A_u + st * A_BYTES;
        const uint32_t Bb = B_u + st * B_BYTES;
        const int k0 = kt << 5;
        const __half* src; int krel;
        if (k0 < split) { src = in1n; krel = k0; } else { src = in2n; krel = k0 - split; }
        // B tile: [k=32][s=128]
        cp16(Bb + (bkk * B_PITCH_H + bcq * 8) * 2,
             src + (size_t)(krel + bkk) * HW + s0 + bcq * 8);
        // A tile: [o=256][k=32], 2 chunks per thread
        cp16(Ab + (am * A_PITCH_H + ac2 * 8) * 2,
             wh + (size_t)(o0 + am) * Cin + k0 + ac2 * 8);
        cp16(Ab + (am * A_PITCH_H + ac2 * 8 + 16) * 2,
             wh + (size_t)(o0 + am) * Cin + k0 + ac2 * 8 + 16);
        cp_commit();
    };

    const uint32_t a_off = ((lane & 15) * A_PITCH_H + (lane >> 4) * 8) * 2;
    const uint32_t b_off = ((lane & 15) * B_PITCH_H + n0w + (lane >> 4) * 8) * 2;

    // preload 2 tiles (T >= 8 in all uses)
    load_tile(0);
    load_tile(1);

    for (int kt = 0; kt < T; kt++) {
        if (kt + 1 < T) { cp_wait<1>(); }
        else            { cp_wait<0>(); }
        __syncthreads();
        if (kt + 2 < T) load_tile(kt + 2);

        const int st = kt % NSTAGE;
        const uint32_t Ab = A_u + st * A_BYTES;
        const uint32_t Bb = B_u + st * B_BYTES;
#pragma unroll
        for (int ks = 0; ks < 2; ks++) {
            const int k16 = ks * 16;
            uint32_t af[4][4], bf[4][2];
#pragma unroll
            for (int mi = 0; mi < 4; mi++)
                ldm_x4(af[mi], Ab + a_off + ((m0w + mi * 16) * A_PITCH_H + k16) * 2);
#pragma unroll
            for (int np = 0; np < 2; np++) {
                uint32_t r[4];
                ldm_x4_t(r, Bb + b_off + (k16 * B_PITCH_H + np * 16) * 2);
                bf[np * 2][0] = r[0]; bf[np * 2][1] = r[1];
                bf[np * 2 + 1][0] = r[2]; bf[np * 2 + 1][1] = r[3];
            }
#pragma unroll
            for (int mi = 0; mi < 4; mi++)
#pragma unroll
                for (int ni = 0; ni < 4; ni++)
                    mma_f16(acc[mi][ni], af[mi][0], af[mi][1], af[mi][2], af[mi][3],
                            bf[ni][0], bf[ni][1]);
        }
    }

    // epilogue
#pragma unroll
    for (int mi = 0; mi < 4; mi++) {
        int r  = m0w + mi * 16 + gid;
        float b_lo = par[r], s_lo = par[BM + r], t_lo = par[2 * BM + r];
        float b_hi = par[r + 8], s_hi = par[BM + r + 8], t_hi = par[2 * BM + r + 8];
        if (out_half) {
            __half* outn = (__half*)outp + (size_t)n * Cout * HW;
            __half* row_lo = outn + (size_t)(o0 + r) * HW + s0;
            __half* row_hi = outn + (size_t)(o0 + r + 8) * HW + s0;
#pragma unroll
            for (int ni = 0; ni < 4; ni++) {
                int cc = n0w + ni * 8 + tg * 2;
                float lx = fmaxf((acc[mi][ni][0] + b_lo) * s_lo + t_lo, 0.f);
                float ly = fmaxf((acc[mi][ni][1] + b_lo) * s_lo + t_lo, 0.f);
                float hx = fmaxf((acc[mi][ni][2] + b_hi) * s_hi + t_hi, 0.f);
                float hy = fmaxf((acc[mi][ni][3] + b_hi) * s_hi + t_hi, 0.f);
                *(__half2*)&row_lo[cc] = __floats2half2_rn(lx, ly);
                *(__half2*)&row_hi[cc] = __floats2half2_rn(hx, hy);
            }
        } else {
            float* outn = (float*)outp + (size_t)n * Cout * HW;
            float* row_lo = outn + (size_t)(o0 + r) * HW + s0;
            float* row_hi = outn + (size_t)(o0 + r + 8) * HW + s0;
#pragma unroll
            for (int ni = 0; ni < 4; ni++) {
                int cc = n0w + ni * 8 + tg * 2;
                float2 lo, hi;
                lo.x = fmaxf((acc[mi][ni][0] + b_lo) * s_lo + t_lo, 0.f);
                lo.y = fmaxf((acc[mi][ni][1] + b_lo) * s_lo + t_lo, 0.f);
                hi.x = fmaxf((acc[mi][ni][2] + b_hi) * s_hi + t_hi, 0.f);
                hi.y = fmaxf((acc[mi][ni][3] + b_hi) * s_hi + t_hi, 0.f);
                *(float2*)&row_lo[cc] = lo;
                *(float2*)&row_hi[cc] = hi;
            }
        }
    }
}

// ---------------- 5) fused attention ----------------
__global__ __launch_bounds__(128) void attn_kernel() {
    const int n = blockIdx.y;
    const int s2 = blockIdx.x * 128 + threadIdx.x;
    const int tid = threadIdx.x;

    __shared__ float kks[KC * K];
    __shared__ float vls[KC * K];
    const float* kkb = g_kk + (size_t)n * KC * K;
    const float* vlb = g_val + (size_t)n * KC * K;
    for (int i = tid; i < KC * K; i += 128) { kks[i] = kkb[i]; vls[i] = vlb[i]; }
    __syncthreads();

    const __half2* q = (const __half2*)(g_q2h + (size_t)n * KC * HW) + s2;
    float2 logit[K];
#pragma unroll
    for (int k = 0; k < K; k++) logit[k] = make_float2(0.f, 0.f);

    for (int c = 0; c < KC; c++) {
        float2 qv = __half22float2(q[(size_t)c * (HW / 2)]);
#pragma unroll
        for (int k = 0; k < K; k++) {
            float kv = kks[c * K + k];
            logit[k].x += qv.x * kv;
            logit[k].y += qv.y * kv;
        }
    }

    float mx = -1e30f, my = -1e30f;
#pragma unroll
    for (int k = 0; k < K; k++) {
        mx = fmaxf(mx, logit[k].x); my = fmaxf(my, logit[k].y);
    }
    float sx = 0.f, sy = 0.f;
#pragma unroll
    for (int k = 0; k < K; k++) {
        logit[k].x = __expf(logit[k].x - mx); sx += logit[k].x;
        logit[k].y = __expf(logit[k].y - my); sy += logit[k].y;
    }
    const float ix = 1.0f / sx, iy = 1.0f / sy;
#pragma unroll
    for (int k = 0; k < K; k++) { logit[k].x *= ix; logit[k].y *= iy; }

    __half2* ctx = (__half2*)(g_ctxh + (size_t)n * KC * HW) + s2;
    for (int c = 0; c < KC; c++) {
        float ax = 0.f, ay = 0.f;
#pragma unroll
        for (int k = 0; k < K; k++) {
            float vv = vls[c * K + k];
            ax += logit[k].x * vv;
            ay += logit[k].y * vv;
        }
        ctx[(size_t)c * (HW / 2)] = __floats2half2_rn(ax, ay);
    }
}

// ---------------- launch ----------------
extern "C" void kernel_launch(void* const* d_in, const int* in_sizes, int n_in,
                              void* d_out, int out_size) {
    (void)in_sizes; (void)n_in; (void)out_size;
    const float* feats = (const float*)d_in[0];
    const float* probs = (const float*)d_in[1];
    const float* wp1 = (const float*)d_in[2];
    const float* bp1 = (const float*)d_in[3];
    const float* sp1 = (const float*)d_in[4];
    const float* tp1 = (const float*)d_in[5];
    const float* wp2 = (const float*)d_in[6];
    const float* bp2 = (const float*)d_in[7];
    const float* sp2 = (const float*)d_in[8];
    const float* tp2 = (const float*)d_in[9];
    const float* wo1 = (const float*)d_in[10];
    const float* bo1 = (const float*)d_in[11];
    const float* so1 = (const float*)d_in[12];
    const float* to1 = (const float*)d_in[13];
    const float* wo2 = (const float*)d_in[14];
    const float* bo2 = (const float*)d_in[15];
    const float* so2 = (const float*)d_in[16];
    const float* to2 = (const float*)d_in[17];
    const float* wd  = (const float*)d_in[18];
    const float* bd  = (const float*)d_in[19];
    const float* sd  = (const float*)d_in[20];
    const float* td  = (const float*)d_in[21];
    const float* wu  = (const float*)d_in[22];
    const float* bu  = (const float*)d_in[23];
    const float* su  = (const float*)d_in[24];
    const float* tu  = (const float*)d_in[25];
    const float* wf  = (const float*)d_in[26];
    const float* bf  = (const float*)d_in[27];
    const float* sf  = (const float*)d_in[28];
    const float* tf  = (const float*)d_in[29];
    float* out = (float*)d_out;

    void *p_proxy, *p_o1, *p_kk, *p_val;
    void *p_featsh, *p_q1h, *p_q2h, *p_ctxh, *p_ctxuph;
    void *p_wp1h, *p_wp2h, *p_wuh, *p_wfh;
    cudaGetSymbolAddress(&p_proxy, g_proxy);
    cudaGetSymbolAddress(&p_o1, g_o1);
    cudaGetSymbolAddress(&p_kk, g_kk);
    cudaGetSymbolAddress(&p_val, g_val);
    cudaGetSymbolAddress(&p_featsh, g_featsh);
    cudaGetSymbolAddress(&p_q1h, g_q1h);
    cudaGetSymbolAddress(&p_q2h, g_q2h);
    cudaGetSymbolAddress(&p_ctxh, g_ctxh);
    cudaGetSymbolAddress(&p_ctxuph, g_ctxuph);
    cudaGetSymbolAddress(&p_wp1h, g_wp1h);
    cudaGetSymbolAddress(&p_wp2h, g_wp2h);
    cudaGetSymbolAddress(&p_wuh, g_wuh);
    cudaGetSymbolAddress(&p_wfh, g_wfh);

    cudaFuncSetAttribute(cbr_gemm_mma, cudaFuncAttributeMaxDynamicSharedMemorySize, GEMM_SMEM);
    cudaFuncSetAttribute(small_cbr2, cudaFuncAttributeMaxDynamicSharedMemorySize, C * 20 * 4);

    static cudaStream_t s2 = nullptr;
    static cudaEvent_t ev_fork = nullptr, ev_feats = nullptr, ev_chainB = nullptr;
    if (s2 == nullptr) {
        cudaStreamCreateWithFlags(&s2, cudaStreamNonBlocking);
        cudaEventCreateWithFlags(&ev_fork, cudaEventDisableTiming);
        cudaEventCreateWithFlags(&ev_feats, cudaEventDisableTiming);
        cudaEventCreateWithFlags(&ev_chainB, cudaEventDisableTiming);
    }

    // ---- fork: chain B (softmax) starts immediately on s2 ----
    cudaEventRecord(ev_fork, 0);
    cudaStreamWaitEvent(s2, ev_fork, 0);
    softmax_kernel<<<NB * K, 512, 0, s2>>>(probs);

    // ---- chain A on stream 0: feats f2h -> weights f2h -> GEMM1 -> GEMM2 ----
    {
        int n4 = NB * C * HW / 4;
        f2h_kernel<<<(n4 + 255) / 256, 256>>>((const float4*)feats, (uint2*)p_featsh, n4);
    }
    cudaEventRecord(ev_feats, 0);
    {
        W4 w;
        w.in[0] = (const float4*)wp1; w.out[0] = (uint2*)p_wp1h;
        w.in[1] = (const float4*)wp2; w.out[1] = (uint2*)p_wp2h;
        w.in[2] = (const float4*)wu;  w.out[2] = (uint2*)p_wuh;
        w.in[3] = (const float4*)wf;  w.out[3] = (uint2*)p_wfh;
        int a = KC * C / 4, b = a + KC * KC / 4, c = b + C * KC / 4, d = c + OUTC * 2 * C / 4;
        w.end[0] = a; w.end[1] = b; w.end[2] = c; w.end[3] = d;
        f2h_weights<<<(d + 255) / 256, 256>>>(w);
    }
    cbr_gemm_mma<<<dim3(HW / 128, KC / BM, NB), 512, GEMM_SMEM>>>(
        (const __half*)p_featsh, nullptr, (const __half*)p_wp1h, bp1, sp1, tp1,
        p_q1h, 1, C, C, KC);
    cbr_gemm_mma<<<dim3(HW / 128, KC / BM, NB), 512, GEMM_SMEM>>>(
        (const __half*)p_q1h, nullptr, (const __half*)p_wp2h, bp2, sp2, tp2,
        p_q2h, 1, KC, KC, KC);

    // ---- chain B on s2: proxy -> reduce -> small_cbrs ----
    cudaStreamWaitEvent(s2, ev_feats, 0);
    proxy_partial2<<<dim3(PCH, NB), 256, 0, s2>>>();
    proxy_reduce<<<(NB * C * K + 255) / 256, 256, 0, s2>>>();
    small_cbr2<<<dim3(NB, 8, 2), 256, C * 20 * 4, s2>>>((const float*)p_proxy,
                                                        wo1, bo1, so1, to1, (float*)p_o1,
                                                        wd, bd, sd, td, (float*)p_val, C, 1.0f);
    small_cbr2<<<dim3(NB, 8, 1), 256, KC * 20 * 4, s2>>>((const float*)p_o1,
                                                         wo2, bo2, so2, to2, (float*)p_kk,
                                                         nullptr, nullptr, nullptr, nullptr, nullptr,
                                                         KC, 0.0625f);
    cudaEventRecord(ev_chainB, s2);

    // ---- join, then attn -> GEMM up -> final GEMM on stream 0 ----
    cudaStreamWaitEvent(0, ev_chainB, 0);
    attn_kernel<<<dim3(HW / 256, NB), 128>>>();

    cbr_gemm_mma<<<dim3(HW / 128, C / BM, NB), 512, GEMM_SMEM>>>(
        (const __half*)p_ctxh, nullptr, (const __half*)p_wuh, bu, su, tu,
        p_ctxuph, 1, KC, KC, C);

    cbr_gemm_mma<<<dim3(HW / 128, OUTC / BM, NB), 512, GEMM_SMEM>>>(
        (const __half*)p_ctxuph, (const __half*)p_featsh, (const __half*)p_wfh, bf, sf, tf,
        out, 0, 2 * C, C, OUTC);
}

// round 14
// speedup vs baseline: 2.2520x; 2.2520x over previous
#include <cuda_runtime.h>
#include <cuda_fp16.h>
#include <cstdint>
#include <math.h>

// Problem constants
static constexpr int NB   = 4;
static constexpr int C    = 512;
static constexpr int HW   = 16384;
static constexpr int K    = 19;
static constexpr int KC   = 256;
static constexpr int OUTC = 512;
static constexpr int PCH  = 128;    // proxy spatial chunks

// ---------------- scratch (device globals, no allocation) ----------------
__device__ float g_p[NB * K * HW];
__device__ float g_ppart[PCH * NB * C * K];
__device__ float g_proxy[NB * C * K];
__device__ float g_o1[NB * KC * K];
__device__ float g_kk[NB * KC * K];
__device__ float g_val[NB * KC * K];
__device__ float g_fpart[NB * OUTC * HW];     // partial of final GEMM (feats half)
__device__ __half g_featsh[NB * C * HW];
__device__ __half g_q1h[NB * KC * HW];
__device__ __half g_q2h[NB * KC * HW];
__device__ __half g_ctxh[NB * KC * HW];
__device__ __half g_ctxuph[NB * C * HW];
__device__ __half g_wp1h[KC * C];
__device__ __half g_wp2h[KC * KC];
__device__ __half g_wuh[C * KC];
__device__ __half g_wfh[OUTC * 2 * C];

// ---------------- PTX helpers ----------------
__device__ __forceinline__ void mma_f16(float* d, uint32_t a0, uint32_t a1, uint32_t a2, uint32_t a3,
                                        uint32_t b0, uint32_t b1) {
    asm volatile(
        "mma.sync.aligned.m16n8k16.row.col.f32.f16.f16.f32 "
        "{%0,%1,%2,%3}, {%4,%5,%6,%7}, {%8,%9}, {%0,%1,%2,%3};\n"
        : "+f"(d[0]), "+f"(d[1]), "+f"(d[2]), "+f"(d[3])
        : "r"(a0), "r"(a1), "r"(a2), "r"(a3), "r"(b0), "r"(b1));
}
__device__ __forceinline__ void ldm_x4(uint32_t* r, uint32_t addr) {
    asm volatile("ldmatrix.sync.aligned.m8n8.x4.shared.b16 {%0,%1,%2,%3}, [%4];"
                 : "=r"(r[0]), "=r"(r[1]), "=r"(r[2]), "=r"(r[3]) : "r"(addr));
}
__device__ __forceinline__ void ldm_x4_t(uint32_t* r, uint32_t addr) {
    asm volatile("ldmatrix.sync.aligned.m8n8.x4.trans.shared.b16 {%0,%1,%2,%3}, [%4];"
                 : "=r"(r[0]), "=r"(r[1]), "=r"(r[2]), "=r"(r[3]) : "r"(addr));
}
__device__ __forceinline__ void cp16(uint32_t saddr, const void* g) {
    asm volatile("cp.async.cg.shared.global [%0], [%1], 16;" :: "r"(saddr), "l"(g) : "memory");
}
__device__ __forceinline__ void cp_commit() { asm volatile("cp.async.commit_group;" ::: "memory"); }
template <int N>
__device__ __forceinline__ void cp_wait() { asm volatile("cp.async.wait_group %0;" :: "n"(N) : "memory"); }

// ---------------- 0) fp32 -> fp16 conversions ----------------
__global__ __launch_bounds__(256) void f2h_kernel(const float4* __restrict__ in,
                                                  uint2* __restrict__ out, int n4) {
    int i = blockIdx.x * 256 + threadIdx.x;
    if (i >= n4) return;
    float4 v = in[i];
    __half2 a = __floats2half2_rn(v.x, v.y);
    __half2 b = __floats2half2_rn(v.z, v.w);
    uint2 t; t.x = *(uint32_t*)&a; t.y = *(uint32_t*)&b;
    out[i] = t;
}

struct W4 {
    const float4* in[4];
    uint2* out[4];
    int end[4];
};
__global__ __launch_bounds__(256) void f2h_weights(W4 w) {
    int i = blockIdx.x * 256 + threadIdx.x;
    int r = 0, base = 0;
    if (i >= w.end[3]) return;
    if (i >= w.end[2])      { r = 3; base = w.end[2]; }
    else if (i >= w.end[1]) { r = 2; base = w.end[1]; }
    else if (i >= w.end[0]) { r = 1; base = w.end[0]; }
    int j = i - base;
    float4 v = w.in[r][j];
    __half2 a = __floats2half2_rn(v.x, v.y);
    __half2 b = __floats2half2_rn(v.z, v.w);
    uint2 t; t.x = *(uint32_t*)&a; t.y = *(uint32_t*)&b;
    w.out[r][j] = t;
}

// ---------------- 1) spatial softmax over probs ----------------
__global__ __launch_bounds__(512) void softmax_kernel(const float* __restrict__ probs) {
    const int row = blockIdx.x;
    const float4* x4 = (const float4*)(probs + (size_t)row * HW);
    float4* y4 = (float4*)(g_p + (size_t)row * HW);
    const int tid = threadIdx.x;
    const int lane = tid & 31, wrp = tid >> 5;
    __shared__ float red[16];

    float m = -1e30f;
    for (int i = tid; i < HW / 4; i += 512) {
        float4 v = x4[i];
        m = fmaxf(fmaxf(m, fmaxf(v.x, v.y)), fmaxf(v.z, v.w));
    }
#pragma unroll
    for (int off = 16; off > 0; off >>= 1) m = fmaxf(m, __shfl_xor_sync(~0u, m, off));
    if (lane == 0) red[wrp] = m;
    __syncthreads();
    m = red[lane & 15];
#pragma unroll
    for (int off = 8; off > 0; off >>= 1) m = fmaxf(m, __shfl_xor_sync(~0u, m, off));

    float sum = 0.f;
    for (int i = tid; i < HW / 4; i += 512) {
        float4 v = x4[i];
        v.x = __expf(v.x - m); v.y = __expf(v.y - m);
        v.z = __expf(v.z - m); v.w = __expf(v.w - m);
        y4[i] = v;
        sum += v.x + v.y + v.z + v.w;
    }
#pragma unroll
    for (int off = 16; off > 0; off >>= 1) sum += __shfl_xor_sync(~0u, sum, off);
    __syncthreads();
    if (lane == 0) red[wrp] = sum;
    __syncthreads();
    sum = red[lane & 15];
#pragma unroll
    for (int off = 8; off > 0; off >>= 1) sum += __shfl_xor_sync(~0u, sum, off);
    const float inv = 1.0f / sum;
    for (int i = tid; i < HW / 4; i += 512) {
        float4 v = y4[i];
        v.x *= inv; v.y *= inv; v.z *= inv; v.w *= inv;
        y4[i] = v;
    }
}

// ---------------- 2) proxy pooling: transposed smem tile ----------------
__global__ __launch_bounds__(256) void proxy_partial2() {
    const int ch = blockIdx.x;
    const int n  = blockIdx.y;
    const int tid = threadIdx.x;

    __shared__ __half sf[32][520];
    __shared__ float sp[19][33];

    float acc[2][K];
#pragma unroll
    for (int h = 0; h < 2; h++)
#pragma unroll
        for (int k = 0; k < K; k++) acc[h][k] = 0.f;

    const __half* fb = g_featsh + (size_t)n * C * HW;
    const float* pb = g_p + (size_t)n * K * HW;
    const int c0 = 2 * tid;
    const int sbeg = ch * (HW / PCH), send = sbeg + (HW / PCH);

    for (int s0 = sbeg; s0 < send; s0 += 32) {
        {
            int c = tid;
#pragma unroll
            for (int h = 0; h < 2; h++, c += 256) {
                const __half* gp = fb + (size_t)c * HW + s0;
#pragma unroll
                for (int q = 0; q < 4; q++) {
                    uint4 v = *(const uint4*)(gp + q * 8);
                    const __half* hh = (const __half*)&v;
#pragma unroll
                    for (int j = 0; j < 8; j++) sf[q * 8 + j][c] = hh[j];
                }
            }
        }
        for (int i = tid; i < K * 32; i += 256) {
            int k = i >> 5, s = i & 31;
            sp[k][s] = pb[(size_t)k * HW + s0 + s];
        }
        __syncthreads();
#pragma unroll 2
        for (int s = 0; s < 32; s++) {
            __half2 hv = *(const __half2*)&sf[s][c0];
            float2 f = __half22float2(hv);
#pragma unroll
            for (int k = 0; k < K; k++) {
                float pv = sp[k][s];
                acc[0][k] += f.x * pv;
                acc[1][k] += f.y * pv;
            }
        }
        __syncthreads();
    }

#pragma unroll
    for (int h = 0; h < 2; h++) {
        float* ob = g_ppart + ((size_t)ch * NB + n) * C * K + (size_t)(c0 + h) * K;
#pragma unroll
        for (int k = 0; k < K; k++) ob[k] = acc[h][k];
    }
}

__global__ __launch_bounds__(256) void proxy_reduce() {
    int e = blockIdx.x * 256 + threadIdx.x;
    if (e >= NB * C * K) return;
    float s = 0.f;
#pragma unroll 8
    for (int ch = 0; ch < PCH; ch++) s += g_ppart[(size_t)ch * NB * C * K + e];
    g_proxy[e] = s;
}

// ---------------- 3) tiny conv1x1+BN+ReLU ----------------
__global__ __launch_bounds__(256) void small_cbr2(const float* __restrict__ in,
                                                  const float* __restrict__ wA,
                                                  const float* __restrict__ bA,
                                                  const float* __restrict__ scA,
                                                  const float* __restrict__ shA,
                                                  float* __restrict__ outA,
                                                  const float* __restrict__ wB,
                                                  const float* __restrict__ bB,
                                                  const float* __restrict__ scB,
                                                  const float* __restrict__ shB,
                                                  float* __restrict__ outB,
                                                  int Cin, float fscale) {
    const int n = blockIdx.x;
    const int ob = blockIdx.y;
    const int tid = threadIdx.x;
    const float* w  = blockIdx.z ? wB : wA;
    const float* b  = blockIdx.z ? bB : bA;
    const float* sc = blockIdx.z ? scB : scA;
    const float* sh = blockIdx.z ? shB : shA;
    float* out      = blockIdx.z ? outB : outA;

    extern __shared__ float sin_[];
    const float* ibase = in + (size_t)n * Cin * K;
    for (int i = tid; i < Cin * 20; i += 256) {
        int c = i / 20, k = i - c * 20;
        sin_[i] = (k < K) ? ibase[c * K + k] : 0.f;
    }
    __syncthreads();

    const int o = ob * 32 + (tid >> 3);
    const int part = tid & 7;

    float acc[K];
#pragma unroll
    for (int k = 0; k < K; k++) acc[k] = 0.f;

    const float* wrow = w + (size_t)o * Cin;
    for (int c = part; c < Cin; c += 8) {
        float wv = wrow[c];
        const float* srow = &sin_[c * 20];
#pragma unroll
        for (int k = 0; k < K; k++) acc[k] += wv * srow[k];
    }
#pragma unroll
    for (int off = 4; off > 0; off >>= 1)
#pragma unroll
        for (int k = 0; k < K; k++) acc[k] += __shfl_down_sync(0xffffffffu, acc[k], off, 8);

    if (part == 0) {
        const float bb = b[o], ss = sc[o], tt = sh[o];
        float* obase = out + ((size_t)n * KC + o) * K;
#pragma unroll
        for (int k = 0; k < K; k++) obase[k] = fmaxf((acc[k] + bb) * ss + tt, 0.f) * fscale;
    }
}

// ---------------- 4) fp16 mma + cp.async(4-stage) + ldmatrix CBR GEMM ----------------
// mode: 0 = fp32 out, BN+ReLU, optional partial-add (part != nullptr)
//       1 = fp16 out, BN+ReLU
//       2 = raw fp32 accumulator out (no BN/ReLU) — partial producer
// wstride: row stride of weight matrix (>= Cin; allows column-sliced weights).
static constexpr int A_PITCH_H = 40;
static constexpr int B_PITCH_H = 136;
static constexpr int A_BYTES = 128 * A_PITCH_H * 2;
static constexpr int B_BYTES = 32 * B_PITCH_H * 2;
static constexpr int NSTAGE = 4;
static constexpr int GEMM_SMEM = NSTAGE * (A_BYTES + B_BYTES) + 3 * 128 * 4;

__global__ __launch_bounds__(256) void cbr_gemm_mma(const __half* __restrict__ in1,
                                                    const __half* __restrict__ in2,
                                                    const __half* __restrict__ wh,
                                                    const float* __restrict__ bias,
                                                    const float* __restrict__ sc,
                                                    const float* __restrict__ sh,
                                                    void* __restrict__ outp, int mode,
                                                    int Cin, int split, int Cout,
                                                    int wstride,
                                                    const float* __restrict__ part) {
    extern __shared__ char smem_c[];
    float* par = (float*)(smem_c + NSTAGE * (A_BYTES + B_BYTES));

    const int tid  = threadIdx.x;
    const int lane = tid & 31;
    const int wid  = tid >> 5;
    const int n    = blockIdx.z;
    const int s0   = blockIdx.x * 128;
    const int o0   = blockIdx.y * 128;

    const int m0w = (wid & 1) * 64;
    const int n0w = (wid >> 1) * 32;
    const int gid = lane >> 2;
    const int tg  = lane & 3;

    uint32_t smem_u32;
    asm("{ .reg .u64 t; cvta.to.shared.u64 t, %1; cvt.u32.u64 %0, t; }" : "=r"(smem_u32) : "l"(smem_c));
    const uint32_t A_u = smem_u32;
    const uint32_t B_u = smem_u32 + NSTAGE * A_BYTES;

    if (mode != 2 && tid < 128) {
        par[tid]       = bias[o0 + tid];
        par[128 + tid] = sc[o0 + tid];
        par[256 + tid] = sh[o0 + tid];
    }

    const int T = Cin >> 5;
    const __half* in1n = in1 + (size_t)n * split * HW;
    const __half* in2n = in2 ? (in2 + (size_t)n * (Cin - split) * HW) : nullptr;

    const int bkk = tid >> 4, bcq = tid & 15;
    const int am  = tid >> 2, acq = tid & 3;

    float acc[4][4][4];
#pragma unroll
    for (int mi = 0; mi < 4; mi++)
#pragma unroll
        for (int ni = 0; ni < 4; ni++)
#pragma unroll
            for (int r = 0; r < 4; r++) acc[mi][ni][r] = 0.f;

    auto load_tile = [&](int kt) {
        const int st = kt & (NSTAGE - 1);
        const uint32_t Ab = A_u + st * A_BYTES;
        const uint32_t Bb = B_u + st * B_BYTES;
        const int k0 = kt << 5;
        const __half* src; int krel;
        if (k0 < split) { src = in1n; krel = k0; } else { src = in2n; krel = k0 - split; }
        cp16(Bb + (bkk * B_PITCH_H + bcq * 8) * 2,
             src + (size_t)(krel + bkk) * HW + s0 + bcq * 8);
        cp16(Bb + ((bkk + 16) * B_PITCH_H + bcq * 8) * 2,
             src + (size_t)(krel + bkk + 16) * HW + s0 + bcq * 8);
        cp16(Ab + (am * A_PITCH_H + acq * 8) * 2,
             wh + (size_t)(o0 + am) * wstride + k0 + acq * 8);
        cp16(Ab + ((am + 64) * A_PITCH_H + acq * 8) * 2,
             wh + (size_t)(o0 + am + 64) * wstride + k0 + acq * 8);
        cp_commit();
    };

    const uint32_t a_off = ((lane & 15) * A_PITCH_H + (lane >> 4) * 8) * 2;
    const uint32_t b_off = ((lane & 15) * B_PITCH_H + n0w + (lane >> 4) * 8) * 2;

    load_tile(0);
    load_tile(1);
    load_tile(2);

    for (int kt = 0; kt < T; kt++) {
        if (kt + 1 >= T)      { cp_wait<0>(); }
        else if (kt + 2 >= T) { cp_wait<1>(); }
        else                  { cp_wait<2>(); }
        __syncthreads();
        if (kt + 3 < T) load_tile(kt + 3);

        const int st = kt & (NSTAGE - 1);
        const uint32_t Ab = A_u + st * A_BYTES;
        const uint32_t Bb = B_u + st * B_BYTES;
#pragma unroll
        for (int ks = 0; ks < 2; ks++) {
            const int k16 = ks * 16;
            uint32_t af[4][4], bf[4][2];
#pragma unroll
            for (int mi = 0; mi < 4; mi++)
                ldm_x4(af[mi], Ab + a_off + ((m0w + mi * 16) * A_PITCH_H + k16) * 2);
#pragma unroll
            for (int np = 0; np < 2; np++) {
                uint32_t r[4];
                ldm_x4_t(r, Bb + b_off + (k16 * B_PITCH_H + np * 16) * 2);
                bf[np * 2][0] = r[0]; bf[np * 2][1] = r[1];
                bf[np * 2 + 1][0] = r[2]; bf[np * 2 + 1][1] = r[3];
            }
#pragma unroll
            for (int mi = 0; mi < 4; mi++)
#pragma unroll
                for (int ni = 0; ni < 4; ni++)
                    mma_f16(acc[mi][ni], af[mi][0], af[mi][1], af[mi][2], af[mi][3],
                            bf[ni][0], bf[ni][1]);
        }
    }

    // epilogue
    const float* partn = part ? (part + (size_t)n * Cout * HW) : nullptr;
#pragma unroll
    for (int mi = 0; mi < 4; mi++) {
        int r  = m0w + mi * 16 + gid;
        if (mode == 1) {
            float b_lo = par[r], s_lo = par[128 + r], t_lo = par[256 + r];
            float b_hi = par[r + 8], s_hi = par[128 + r + 8], t_hi = par[256 + r + 8];
            __half* outn = (__half*)outp + (size_t)n * Cout * HW;
            __half* row_lo = outn + (size_t)(o0 + r) * HW + s0;
            __half* row_hi = outn + (size_t)(o0 + r + 8) * HW + s0;
#pragma unroll
            for (int ni = 0; ni < 4; ni++) {
                int cc = n0w + ni * 8 + tg * 2;
                float lx = fmaxf((acc[mi][ni][0] + b_lo) * s_lo + t_lo, 0.f);
                float ly = fmaxf((acc[mi][ni][1] + b_lo) * s_lo + t_lo, 0.f);
                float hx = fmaxf((acc[mi][ni][2] + b_hi) * s_hi + t_hi, 0.f);
                float hy = fmaxf((acc[mi][ni][3] + b_hi) * s_hi + t_hi, 0.f);
                *(__half2*)&row_lo[cc] = __floats2half2_rn(lx, ly);
                *(__half2*)&row_hi[cc] = __floats2half2_rn(hx, hy);
            }
        } else if (mode == 2) {
            float* outn = (float*)outp + (size_t)n * Cout * HW;
            float* row_lo = outn + (size_t)(o0 + r) * HW + s0;
            float* row_hi = outn + (size_t)(o0 + r + 8) * HW + s0;
#pragma unroll
            for (int ni = 0; ni < 4; ni++) {
                int cc = n0w + ni * 8 + tg * 2;
                float2 lo, hi;
                lo.x = acc[mi][ni][0]; lo.y = acc[mi][ni][1];
                hi.x = acc[mi][ni][2]; hi.y = acc[mi][ni][3];
                *(float2*)&row_lo[cc] = lo;
                *(float2*)&row_hi[cc] = hi;
            }
        } else {
            float b_lo = par[r], s_lo = par[128 + r], t_lo = par[256 + r];
            float b_hi = par[r + 8], s_hi = par[128 + r + 8], t_hi = par[256 + r + 8];
            float* outn = (float*)outp + (size_t)n * Cout * HW;
            float* row_lo = outn + (size_t)(o0 + r) * HW + s0;
            float* row_hi = outn + (size_t)(o0 + r + 8) * HW + s0;
            const float* prow_lo = partn ? partn + (size_t)(o0 + r) * HW + s0 : nullptr;
            const float* prow_hi = partn ? partn + (size_t)(o0 + r + 8) * HW + s0 : nullptr;
#pragma unroll
            for (int ni = 0; ni < 4; ni++) {
                int cc = n0w + ni * 8 + tg * 2;
                float a0 = acc[mi][ni][0], a1 = acc[mi][ni][1];
                float a2 = acc[mi][ni][2], a3 = acc[mi][ni][3];
                if (partn) {
                    float2 pl = *(const float2*)&prow_lo[cc];
                    float2 ph = *(const float2*)&prow_hi[cc];
                    a0 += pl.x; a1 += pl.y; a2 += ph.x; a3 += ph.y;
                }
                float2 lo, hi;
                lo.x = fmaxf((a0 + b_lo) * s_lo + t_lo, 0.f);
                lo.y = fmaxf((a1 + b_lo) * s_lo + t_lo, 0.f);
                hi.x = fmaxf((a2 + b_hi) * s_hi + t_hi, 0.f);
                hi.y = fmaxf((a3 + b_hi) * s_hi + t_hi, 0.f);
                *(float2*)&row_lo[cc] = lo;
                *(float2*)&row_hi[cc] = hi;
            }
        }
    }
}

// ---------------- 5) fused attention ----------------
__global__ __launch_bounds__(128) void attn_kernel() {
    const int n = blockIdx.y;
    const int s2 = blockIdx.x * 128 + threadIdx.x;
    const int tid = threadIdx.x;

    __shared__ float kks[KC * K];
    __shared__ float vls[KC * K];
    const float* kkb = g_kk + (size_t)n * KC * K;
    const float* vlb = g_val + (size_t)n * KC * K;
    for (int i = tid; i < KC * K; i += 128) { kks[i] = kkb[i]; vls[i] = vlb[i]; }
    __syncthreads();

    const __half2* q = (const __half2*)(g_q2h + (size_t)n * KC * HW) + s2;
    float2 logit[K];
#pragma unroll
    for (int k = 0; k < K; k++) logit[k] = make_float2(0.f, 0.f);

    for (int c = 0; c < KC; c++) {
        float2 qv = __half22float2(q[(size_t)c * (HW / 2)]);
#pragma unroll
        for (int k = 0; k < K; k++) {
            float kv = kks[c * K + k];
            logit[k].x += qv.x * kv;
            logit[k].y += qv.y * kv;
        }
    }

    float mx = -1e30f, my = -1e30f;
#pragma unroll
    for (int k = 0; k < K; k++) {
        mx = fmaxf(mx, logit[k].x); my = fmaxf(my, logit[k].y);
    }
    float sx = 0.f, sy = 0.f;
#pragma unroll
    for (int k = 0; k < K; k++) {
        logit[k].x = __expf(logit[k].x - mx); sx += logit[k].x;
        logit[k].y = __expf(logit[k].y - my); sy += logit[k].y;
    }
    const float ix = 1.0f / sx, iy = 1.0f / sy;
#pragma unroll
    for (int k = 0; k < K; k++) { logit[k].x *= ix; logit[k].y *= iy; }

    __half2* ctx = (__half2*)(g_ctxh + (size_t)n * KC * HW) + s2;
    for (int c = 0; c < KC; c++) {
        float ax = 0.f, ay = 0.f;
#pragma unroll
        for (int k = 0; k < K; k++) {
            float vv = vls[c * K + k];
            ax += logit[k].x * vv;
            ay += logit[k].y * vv;
        }
        ctx[(size_t)c * (HW / 2)] = __floats2half2_rn(ax, ay);
    }
}

// ---------------- launch ----------------
extern "C" void kernel_launch(void* const* d_in, const int* in_sizes, int n_in,
                              void* d_out, int out_size) {
    (void)in_sizes; (void)n_in; (void)out_size;
    const float* feats = (const float*)d_in[0];
    const float* probs = (const float*)d_in[1];
    const float* wp1 = (const float*)d_in[2];
    const float* bp1 = (const float*)d_in[3];
    const float* sp1 = (const float*)d_in[4];
    const float* tp1 = (const float*)d_in[5];
    const float* wp2 = (const float*)d_in[6];
    const float* bp2 = (const float*)d_in[7];
    const float* sp2 = (const float*)d_in[8];
    const float* tp2 = (const float*)d_in[9];
    const float* wo1 = (const float*)d_in[10];
    const float* bo1 = (const float*)d_in[11];
    const float* so1 = (const float*)d_in[12];
    const float* to1 = (const float*)d_in[13];
    const float* wo2 = (const float*)d_in[14];
    const float* bo2 = (const float*)d_in[15];
    const float* so2 = (const float*)d_in[16];
    const float* to2 = (const float*)d_in[17];
    const float* wd  = (const float*)d_in[18];
    const float* bd  = (const float*)d_in[19];
    const float* sd  = (const float*)d_in[20];
    const float* td  = (const float*)d_in[21];
    const float* wu  = (const float*)d_in[22];
    const float* bu  = (const float*)d_in[23];
    const float* su  = (const float*)d_in[24];
    const float* tu  = (const float*)d_in[25];
    const float* wf  = (const float*)d_in[26];
    const float* bf  = (const float*)d_in[27];
    const float* sf  = (const float*)d_in[28];
    const float* tf  = (const float*)d_in[29];
    float* out = (float*)d_out;

    void *p_proxy, *p_o1, *p_kk, *p_val, *p_fpart;
    void *p_featsh, *p_q1h, *p_q2h, *p_ctxh, *p_ctxuph;
    void *p_wp1h, *p_wp2h, *p_wuh, *p_wfh;
    cudaGetSymbolAddress(&p_proxy, g_proxy);
    cudaGetSymbolAddress(&p_o1, g_o1);
    cudaGetSymbolAddress(&p_kk, g_kk);
    cudaGetSymbolAddress(&p_val, g_val);
    cudaGetSymbolAddress(&p_fpart, g_fpart);
    cudaGetSymbolAddress(&p_featsh, g_featsh);
    cudaGetSymbolAddress(&p_q1h, g_q1h);
    cudaGetSymbolAddress(&p_q2h, g_q2h);
    cudaGetSymbolAddress(&p_ctxh, g_ctxh);
    cudaGetSymbolAddress(&p_ctxuph, g_ctxuph);
    cudaGetSymbolAddress(&p_wp1h, g_wp1h);
    cudaGetSymbolAddress(&p_wp2h, g_wp2h);
    cudaGetSymbolAddress(&p_wuh, g_wuh);
    cudaGetSymbolAddress(&p_wfh, g_wfh);

    cudaFuncSetAttribute(cbr_gemm_mma, cudaFuncAttributeMaxDynamicSharedMemorySize, GEMM_SMEM);
    cudaFuncSetAttribute(small_cbr2, cudaFuncAttributeMaxDynamicSharedMemorySize, C * 20 * 4);

    static cudaStream_t s2 = nullptr;
    static cudaEvent_t ev_fork = nullptr, ev_feats = nullptr, ev_w = nullptr,
                       ev_chainB = nullptr, ev_part = nullptr;
    if (s2 == nullptr) {
        cudaStreamCreateWithFlags(&s2, cudaStreamNonBlocking);
        cudaEventCreateWithFlags(&ev_fork, cudaEventDisableTiming);
        cudaEventCreateWithFlags(&ev_feats, cudaEventDisableTiming);
        cudaEventCreateWithFlags(&ev_w, cudaEventDisableTiming);
        cudaEventCreateWithFlags(&ev_chainB, cudaEventDisableTiming);
        cudaEventCreateWithFlags(&ev_part, cudaEventDisableTiming);
    }

    // ---- fork: chain B (softmax) starts immediately on s2 ----
    cudaEventRecord(ev_fork, 0);
    cudaStreamWaitEvent(s2, ev_fork, 0);
    softmax_kernel<<<NB * K, 512, 0, s2>>>(probs);

    // ---- chain A on stream 0: feats f2h -> weights f2h -> GEMM1 -> GEMM2 ----
    {
        int n4 = NB * C * HW / 4;
        f2h_kernel<<<(n4 + 255) / 256, 256>>>((const float4*)feats, (uint2*)p_featsh, n4);
    }
    cudaEventRecord(ev_feats, 0);
    {
        W4 w;
        w.in[0] = (const float4*)wp1; w.out[0] = (uint2*)p_wp1h;
        w.in[1] = (const float4*)wp2; w.out[1] = (uint2*)p_wp2h;
        w.in[2] = (const float4*)wu;  w.out[2] = (uint2*)p_wuh;
        w.in[3] = (const float4*)wf;  w.out[3] = (uint2*)p_wfh;
        int a = KC * C / 4, b = a + KC * KC / 4, c = b + C * KC / 4, d = c + OUTC * 2 * C / 4;
        w.end[0] = a; w.end[1] = b; w.end[2] = c; w.end[3] = d;
        f2h_weights<<<(d + 255) / 256, 256>>>(w);
    }
    cudaEventRecord(ev_w, 0);
    cbr_gemm_mma<<<dim3(HW / 128, KC / 128, NB), 256, GEMM_SMEM>>>(
        (const __half*)p_featsh, nullptr, (const __half*)p_wp1h, bp1, sp1, tp1,
        p_q1h, 1, C, C, KC, C, nullptr);
    cbr_gemm_mma<<<dim3(HW / 128, KC / 128, NB), 256, GEMM_SMEM>>>(
        (const __half*)p_q1h, nullptr, (const __half*)p_wp2h, bp2, sp2, tp2,
        p_q2h, 1, KC, KC, KC, KC, nullptr);

    // ---- chain B on s2: proxy -> reduce -> small_cbrs, then partial final GEMM ----
    cudaStreamWaitEvent(s2, ev_feats, 0);
    proxy_partial2<<<dim3(PCH, NB), 256, 0, s2>>>();
    proxy_reduce<<<(NB * C * K + 255) / 256, 256, 0, s2>>>();
    small_cbr2<<<dim3(NB, 8, 2), 256, C * 20 * 4, s2>>>((const float*)p_proxy,
                                                        wo1, bo1, so1, to1, (float*)p_o1,
                                                        wd, bd, sd, td, (float*)p_val, C, 1.0f);
    small_cbr2<<<dim3(NB, 8, 1), 256, KC * 20 * 4, s2>>>((const float*)p_o1,
                                                         wo2, bo2, so2, to2, (float*)p_kk,
                                                         nullptr, nullptr, nullptr, nullptr, nullptr,
                                                         KC, 0.0625f);
    cudaEventRecord(ev_chainB, s2);

    // partial of final GEMM: feats half (wf columns 512..1023), raw fp32 output.
    // Runs on s2 concurrently with attn + GEMM-up on stream 0.
    cudaStreamWaitEvent(s2, ev_w, 0);
    cbr_gemm_mma<<<dim3(HW / 128, OUTC / 128, NB), 256, GEMM_SMEM, s2>>>(
        (const __half*)p_featsh, nullptr, (const __half*)p_wfh + C, nullptr, nullptr, nullptr,
        p_fpart, 2, C, C, OUTC, 2 * C, nullptr);
    cudaEventRecord(ev_part, s2);

    // ---- join, then attn -> GEMM up on stream 0 ----
    cudaStreamWaitEvent(0, ev_chainB, 0);
    attn_kernel<<<dim3(HW / 256, NB), 128>>>();

    cbr_gemm_mma<<<dim3(HW / 128, C / 128, NB), 256, GEMM_SMEM>>>(
        (const __half*)p_ctxh, nullptr, (const __half*)p_wuh, bu, su, tu,
        p_ctxuph, 1, KC, KC, C, KC, nullptr);

    // ---- final: ctx_up half (wf columns 0..511) + partial add ----
    cudaStreamWaitEvent(0, ev_part, 0);
    cbr_gemm_mma<<<dim3(HW / 128, OUTC / 128, NB), 256, GEMM_SMEM>>>(
        (const __half*)p_ctxuph, nullptr, (const __half*)p_wfh, bf, sf, tf,
        out, 0, C, C, OUTC, 2 * C, (const float*)p_fpart);
}

// round 15
// speedup vs baseline: 2.4717x; 1.0975x over previous
#include <cuda_runtime.h>
#include <cuda_fp16.h>
#include <cstdint>
#include <math.h>

// Problem constants
static constexpr int NB   = 4;
static constexpr int C    = 512;
static constexpr int HW   = 16384;
static constexpr int K    = 19;
static constexpr int KC   = 256;
static constexpr int OUTC = 512;
static constexpr int PCH  = 128;    // proxy spatial chunks

// ---------------- scratch (device globals, no allocation) ----------------
__device__ float g_p[NB * K * HW];
__device__ float g_ppart[PCH * NB * C * K];
__device__ float g_proxy[NB * C * K];
__device__ float g_o1[NB * KC * K];
__device__ float g_kk[NB * KC * K];
__device__ float g_val[NB * KC * K];
__device__ __half g_featsh[NB * C * HW];
__device__ __half g_q1h[NB * KC * HW];
__device__ __half g_q2h[NB * KC * HW];
__device__ __half g_ctxh[NB * KC * HW];
__device__ __half g_ctxuph[NB * C * HW];
__device__ __half g_wp1h[KC * C];
__device__ __half g_wp2h[KC * KC];
__device__ __half g_wuh[C * KC];
__device__ __half g_wfh[OUTC * 2 * C];

// ---------------- PTX helpers ----------------
__device__ __forceinline__ void mma_f16(float* d, uint32_t a0, uint32_t a1, uint32_t a2, uint32_t a3,
                                        uint32_t b0, uint32_t b1) {
    asm volatile(
        "mma.sync.aligned.m16n8k16.row.col.f32.f16.f16.f32 "
        "{%0,%1,%2,%3}, {%4,%5,%6,%7}, {%8,%9}, {%0,%1,%2,%3};\n"
        : "+f"(d[0]), "+f"(d[1]), "+f"(d[2]), "+f"(d[3])
        : "r"(a0), "r"(a1), "r"(a2), "r"(a3), "r"(b0), "r"(b1));
}
__device__ __forceinline__ void ldm_x4(uint32_t* r, uint32_t addr) {
    asm volatile("ldmatrix.sync.aligned.m8n8.x4.shared.b16 {%0,%1,%2,%3}, [%4];"
                 : "=r"(r[0]), "=r"(r[1]), "=r"(r[2]), "=r"(r[3]) : "r"(addr));
}
__device__ __forceinline__ void ldm_x4_t(uint32_t* r, uint32_t addr) {
    asm volatile("ldmatrix.sync.aligned.m8n8.x4.trans.shared.b16 {%0,%1,%2,%3}, [%4];"
                 : "=r"(r[0]), "=r"(r[1]), "=r"(r[2]), "=r"(r[3]) : "r"(addr));
}
__device__ __forceinline__ void cp16(uint32_t saddr, const void* g) {
    asm volatile("cp.async.cg.shared.global [%0], [%1], 16;" :: "r"(saddr), "l"(g) : "memory");
}
__device__ __forceinline__ void cp_commit() { asm volatile("cp.async.commit_group;" ::: "memory"); }
template <int N>
__device__ __forceinline__ void cp_wait() { asm volatile("cp.async.wait_group %0;" :: "n"(N) : "memory"); }

// ---------------- 0) fp32 -> fp16 conversions ----------------
__global__ __launch_bounds__(256) void f2h_kernel(const float4* __restrict__ in,
                                                  uint2* __restrict__ out, int n4) {
    int i = blockIdx.x * 256 + threadIdx.x;
    if (i >= n4) return;
    float4 v = in[i];
    __half2 a = __floats2half2_rn(v.x, v.y);
    __half2 b = __floats2half2_rn(v.z, v.w);
    uint2 t; t.x = *(uint32_t*)&a; t.y = *(uint32_t*)&b;
    out[i] = t;
}

struct W4 {
    const float4* in[4];
    uint2* out[4];
    int end[4];
};
__global__ __launch_bounds__(256) void f2h_weights(W4 w) {
    int i = blockIdx.x * 256 + threadIdx.x;
    int r = 0, base = 0;
    if (i >= w.end[3]) return;
    if (i >= w.end[2])      { r = 3; base = w.end[2]; }
    else if (i >= w.end[1]) { r = 2; base = w.end[1]; }
    else if (i >= w.end[0]) { r = 1; base = w.end[0]; }
    int j = i - base;
    float4 v = w.in[r][j];
    __half2 a = __floats2half2_rn(v.x, v.y);
    __half2 b = __floats2half2_rn(v.z, v.w);
    uint2 t; t.x = *(uint32_t*)&a; t.y = *(uint32_t*)&b;
    w.out[r][j] = t;
}

// ---------------- 1) spatial softmax over probs ----------------
__global__ __launch_bounds__(512) void softmax_kernel(const float* __restrict__ probs) {
    const int row = blockIdx.x;
    const float4* x4 = (const float4*)(probs + (size_t)row * HW);
    float4* y4 = (float4*)(g_p + (size_t)row * HW);
    const int tid = threadIdx.x;
    const int lane = tid & 31, wrp = tid >> 5;
    __shared__ float red[16];

    float m = -1e30f;
    for (int i = tid; i < HW / 4; i += 512) {
        float4 v = x4[i];
        m = fmaxf(fmaxf(m, fmaxf(v.x, v.y)), fmaxf(v.z, v.w));
    }
#pragma unroll
    for (int off = 16; off > 0; off >>= 1) m = fmaxf(m, __shfl_xor_sync(~0u, m, off));
    if (lane == 0) red[wrp] = m;
    __syncthreads();
    m = red[lane & 15];
#pragma unroll
    for (int off = 8; off > 0; off >>= 1) m = fmaxf(m, __shfl_xor_sync(~0u, m, off));

    float sum = 0.f;
    for (int i = tid; i < HW / 4; i += 512) {
        float4 v = x4[i];
        v.x = __expf(v.x - m); v.y = __expf(v.y - m);
        v.z = __expf(v.z - m); v.w = __expf(v.w - m);
        y4[i] = v;
        sum += v.x + v.y + v.z + v.w;
    }
#pragma unroll
    for (int off = 16; off > 0; off >>= 1) sum += __shfl_xor_sync(~0u, sum, off);
    __syncthreads();
    if (lane == 0) red[wrp] = sum;
    __syncthreads();
    sum = red[lane & 15];
#pragma unroll
    for (int off = 8; off > 0; off >>= 1) sum += __shfl_xor_sync(~0u, sum, off);
    const float inv = 1.0f / sum;
    for (int i = tid; i < HW / 4; i += 512) {
        float4 v = y4[i];
        v.x *= inv; v.y *= inv; v.z *= inv; v.w *= inv;
        y4[i] = v;
    }
}

// ---------------- 2) proxy pooling: transposed smem tile ----------------
__global__ __launch_bounds__(256) void proxy_partial2() {
    const int ch = blockIdx.x;
    const int n  = blockIdx.y;
    const int tid = threadIdx.x;

    __shared__ __half sf[32][520];
    __shared__ float sp[19][33];

    float acc[2][K];
#pragma unroll
    for (int h = 0; h < 2; h++)
#pragma unroll
        for (int k = 0; k < K; k++) acc[h][k] = 0.f;

    const __half* fb = g_featsh + (size_t)n * C * HW;
    const float* pb = g_p + (size_t)n * K * HW;
    const int c0 = 2 * tid;
    const int sbeg = ch * (HW / PCH), send = sbeg + (HW / PCH);

    for (int s0 = sbeg; s0 < send; s0 += 32) {
        {
            int c = tid;
#pragma unroll
            for (int h = 0; h < 2; h++, c += 256) {
                const __half* gp = fb + (size_t)c * HW + s0;
#pragma unroll
                for (int q = 0; q < 4; q++) {
                    uint4 v = *(const uint4*)(gp + q * 8);
                    const __half* hh = (const __half*)&v;
#pragma unroll
                    for (int j = 0; j < 8; j++) sf[q * 8 + j][c] = hh[j];
                }
            }
        }
        for (int i = tid; i < K * 32; i += 256) {
            int k = i >> 5, s = i & 31;
            sp[k][s] = pb[(size_t)k * HW + s0 + s];
        }
        __syncthreads();
#pragma unroll 2
        for (int s = 0; s < 32; s++) {
            __half2 hv = *(const __half2*)&sf[s][c0];
            float2 f = __half22float2(hv);
#pragma unroll
            for (int k = 0; k < K; k++) {
                float pv = sp[k][s];
                acc[0][k] += f.x * pv;
                acc[1][k] += f.y * pv;
            }
        }
        __syncthreads();
    }

#pragma unroll
    for (int h = 0; h < 2; h++) {
        float* ob = g_ppart + ((size_t)ch * NB + n) * C * K + (size_t)(c0 + h) * K;
#pragma unroll
        for (int k = 0; k < K; k++) ob[k] = acc[h][k];
    }
}

__global__ __launch_bounds__(256) void proxy_reduce() {
    int e = blockIdx.x * 256 + threadIdx.x;
    if (e >= NB * C * K) return;
    float s = 0.f;
#pragma unroll 8
    for (int ch = 0; ch < PCH; ch++) s += g_ppart[(size_t)ch * NB * C * K + e];
    g_proxy[e] = s;
}

// ---------------- 3) tiny conv1x1+BN+ReLU ----------------
__global__ __launch_bounds__(256) void small_cbr2(const float* __restrict__ in,
                                                  const float* __restrict__ wA,
                                                  const float* __restrict__ bA,
                                                  const float* __restrict__ scA,
                                                  const float* __restrict__ shA,
                                                  float* __restrict__ outA,
                                                  const float* __restrict__ wB,
                                                  const float* __restrict__ bB,
                                                  const float* __restrict__ scB,
                                                  const float* __restrict__ shB,
                                                  float* __restrict__ outB,
                                                  int Cin, float fscale) {
    const int n = blockIdx.x;
    const int ob = blockIdx.y;
    const int tid = threadIdx.x;
    const float* w  = blockIdx.z ? wB : wA;
    const float* b  = blockIdx.z ? bB : bA;
    const float* sc = blockIdx.z ? scB : scA;
    const float* sh = blockIdx.z ? shB : shA;
    float* out      = blockIdx.z ? outB : outA;

    extern __shared__ float sin_[];
    const float* ibase = in + (size_t)n * Cin * K;
    for (int i = tid; i < Cin * 20; i += 256) {
        int c = i / 20, k = i - c * 20;
        sin_[i] = (k < K) ? ibase[c * K + k] : 0.f;
    }
    __syncthreads();

    const int o = ob * 32 + (tid >> 3);
    const int part = tid & 7;

    float acc[K];
#pragma unroll
    for (int k = 0; k < K; k++) acc[k] = 0.f;

    const float* wrow = w + (size_t)o * Cin;
    for (int c = part; c < Cin; c += 8) {
        float wv = wrow[c];
        const float* srow = &sin_[c * 20];
#pragma unroll
        for (int k = 0; k < K; k++) acc[k] += wv * srow[k];
    }
#pragma unroll
    for (int off = 4; off > 0; off >>= 1)
#pragma unroll
        for (int k = 0; k < K; k++) acc[k] += __shfl_down_sync(0xffffffffu, acc[k], off, 8);

    if (part == 0) {
        const float bb = b[o], ss = sc[o], tt = sh[o];
        float* obase = out + ((size_t)n * KC + o) * K;
#pragma unroll
        for (int k = 0; k < K; k++) obase[k] = fmaxf((acc[k] + bb) * ss + tt, 0.f) * fscale;
    }
}

// ---------------- 4) fp16 mma CBR GEMM: 6-stage cp.async, 2 tiles per sync ----------------
static constexpr int A_PITCH_H = 40;
static constexpr int B_PITCH_H = 136;
static constexpr int A_BYTES = 128 * A_PITCH_H * 2;  // 10240
static constexpr int B_BYTES = 32 * B_PITCH_H * 2;   // 8704
static constexpr int NSTAGE = 6;
static constexpr int GEMM_SMEM = NSTAGE * (A_BYTES + B_BYTES) + 3 * 128 * 4;  // 115200

__global__ __launch_bounds__(256) void cbr_gemm_mma(const __half* __restrict__ in1,
                                                    const __half* __restrict__ in2,
                                                    const __half* __restrict__ wh,
                                                    const float* __restrict__ bias,
                                                    const float* __restrict__ sc,
                                                    const float* __restrict__ sh,
                                                    void* __restrict__ outp, int out_half,
                                                    int Cin, int split, int Cout) {
    extern __shared__ char smem_c[];
    float* par = (float*)(smem_c + NSTAGE * (A_BYTES + B_BYTES));

    const int tid  = threadIdx.x;
    const int lane = tid & 31;
    const int wid  = tid >> 5;
    const int n    = blockIdx.z;
    const int s0   = blockIdx.y * 128;   // grid swapped: o-blocks fastest for L2 B-reuse
    const int o0   = blockIdx.x * 128;

    const int m0w = (wid & 1) * 64;
    const int n0w = (wid >> 1) * 32;
    const int gid = lane >> 2;
    const int tg  = lane & 3;

    uint32_t smem_u32;
    asm("{ .reg .u64 t; cvta.to.shared.u64 t, %1; cvt.u32.u64 %0, t; }" : "=r"(smem_u32) : "l"(smem_c));
    const uint32_t A_u = smem_u32;
    const uint32_t B_u = smem_u32 + NSTAGE * A_BYTES;

    if (tid < 128) {
        par[tid]       = bias[o0 + tid];
        par[128 + tid] = sc[o0 + tid];
        par[256 + tid] = sh[o0 + tid];
    }

    const int T = Cin >> 5;   // even (>= 8) in all uses
    const __half* in1n = in1 + (size_t)n * split * HW;
    const __half* in2n = in2 ? (in2 + (size_t)n * (Cin - split) * HW) : nullptr;

    const int bkk = tid >> 4, bcq = tid & 15;
    const int am  = tid >> 2, acq = tid & 3;

    float acc[4][4][4];
#pragma unroll
    for (int mi = 0; mi < 4; mi++)
#pragma unroll
        for (int ni = 0; ni < 4; ni++)
#pragma unroll
            for (int r = 0; r < 4; r++) acc[mi][ni][r] = 0.f;

    auto load_tile = [&](int kt) {
        const int st = kt % NSTAGE;
        const uint32_t Ab = A_u + st * A_BYTES;
        const uint32_t Bb = B_u + st * B_BYTES;
        const int k0 = kt << 5;
        const __half* src; int krel;
        if (k0 < split) { src = in1n; krel = k0; } else { src = in2n; krel = k0 - split; }
        cp16(Bb + (bkk * B_PITCH_H + bcq * 8) * 2,
             src + (size_t)(krel + bkk) * HW + s0 + bcq * 8);
        cp16(Bb + ((bkk + 16) * B_PITCH_H + bcq * 8) * 2,
             src + (size_t)(krel + bkk + 16) * HW + s0 + bcq * 8);
        cp16(Ab + (am * A_PITCH_H + acq * 8) * 2,
             wh + (size_t)(o0 + am) * Cin + k0 + acq * 8);
        cp16(Ab + ((am + 64) * A_PITCH_H + acq * 8) * 2,
             wh + (size_t)(o0 + am + 64) * Cin + k0 + acq * 8);
        cp_commit();
    };

    const uint32_t a_off = ((lane & 15) * A_PITCH_H + (lane >> 4) * 8) * 2;
    const uint32_t b_off = ((lane & 15) * B_PITCH_H + n0w + (lane >> 4) * 8) * 2;

    auto compute_tile = [&](int kt) {
        const int st = kt % NSTAGE;
        const uint32_t Ab = A_u + st * A_BYTES;
        const uint32_t Bb = B_u + st * B_BYTES;
#pragma unroll
        for (int ks = 0; ks < 2; ks++) {
            const int k16 = ks * 16;
            uint32_t af[4][4], bf[4][2];
#pragma unroll
            for (int mi = 0; mi < 4; mi++)
                ldm_x4(af[mi], Ab + a_off + ((m0w + mi * 16) * A_PITCH_H + k16) * 2);
#pragma unroll
            for (int np = 0; np < 2; np++) {
                uint32_t r[4];
                ldm_x4_t(r, Bb + b_off + (k16 * B_PITCH_H + np * 16) * 2);
                bf[np * 2][0] = r[0]; bf[np * 2][1] = r[1];
                bf[np * 2 + 1][0] = r[2]; bf[np * 2 + 1][1] = r[3];
            }
#pragma unroll
            for (int mi = 0; mi < 4; mi++)
#pragma unroll
                for (int ni = 0; ni < 4; ni++)
                    mma_f16(acc[mi][ni], af[mi][0], af[mi][1], af[mi][2], af[mi][3],
                            bf[ni][0], bf[ni][1]);
        }
    };

    // preload 4 tiles (T >= 8 in all uses)
    load_tile(0);
    load_tile(1);
    load_tile(2);
    load_tile(3);

    for (int kt = 0; kt < T; kt += 2) {
        if (kt + 2 >= T) { cp_wait<0>(); }
        else             { cp_wait<2>(); }
        __syncthreads();   // all warps done with tiles kt-2, kt-1 (their buffers are reused by kt+4, kt+5)
        if (kt + 4 < T) { load_tile(kt + 4); load_tile(kt + 5); }
        compute_tile(kt);
        compute_tile(kt + 1);
    }

    // epilogue
#pragma unroll
    for (int mi = 0; mi < 4; mi++) {
        int r  = m0w + mi * 16 + gid;
        float b_lo = par[r], s_lo = par[128 + r], t_lo = par[256 + r];
        float b_hi = par[r + 8], s_hi = par[128 + r + 8], t_hi = par[256 + r + 8];
        if (out_half) {
            __half* outn = (__half*)outp + (size_t)n * Cout * HW;
            __half* row_lo = outn + (size_t)(o0 + r) * HW + s0;
            __half* row_hi = outn + (size_t)(o0 + r + 8) * HW + s0;
#pragma unroll
            for (int ni = 0; ni < 4; ni++) {
                int cc = n0w + ni * 8 + tg * 2;
                float lx = fmaxf((acc[mi][ni][0] + b_lo) * s_lo + t_lo, 0.f);
                float ly = fmaxf((acc[mi][ni][1] + b_lo) * s_lo + t_lo, 0.f);
                float hx = fmaxf((acc[mi][ni][2] + b_hi) * s_hi + t_hi, 0.f);
                float hy = fmaxf((acc[mi][ni][3] + b_hi) * s_hi + t_hi, 0.f);
                *(__half2*)&row_lo[cc] = __floats2half2_rn(lx, ly);
                *(__half2*)&row_hi[cc] = __floats2half2_rn(hx, hy);
            }
        } else {
            float* outn = (float*)outp + (size_t)n * Cout * HW;
            float* row_lo = outn + (size_t)(o0 + r) * HW + s0;
            float* row_hi = outn + (size_t)(o0 + r + 8) * HW + s0;
#pragma unroll
            for (int ni = 0; ni < 4; ni++) {
                int cc = n0w + ni * 8 + tg * 2;
                float2 lo, hi;
                lo.x = fmaxf((acc[mi][ni][0] + b_lo) * s_lo + t_lo, 0.f);
                lo.y = fmaxf((acc[mi][ni][1] + b_lo) * s_lo + t_lo, 0.f);
                hi.x = fmaxf((acc[mi][ni][2] + b_hi) * s_hi + t_hi, 0.f);
                hi.y = fmaxf((acc[mi][ni][3] + b_hi) * s_hi + t_hi, 0.f);
                *(float2*)&row_lo[cc] = lo;
                *(float2*)&row_hi[cc] = hi;
            }
        }
    }
}

// ---------------- 5) fused attention ----------------
__global__ __launch_bounds__(128) void attn_kernel() {
    const int n = blockIdx.y;
    const int s2 = blockIdx.x * 128 + threadIdx.x;
    const int tid = threadIdx.x;

    __shared__ float kks[KC * K];
    __shared__ float vls[KC * K];
    const float* kkb = g_kk + (size_t)n * KC * K;
    const float* vlb = g_val + (size_t)n * KC * K;
    for (int i = tid; i < KC * K; i += 128) { kks[i] = kkb[i]; vls[i] = vlb[i]; }
    __syncthreads();

    const __half2* q = (const __half2*)(g_q2h + (size_t)n * KC * HW) + s2;
    float2 logit[K];
#pragma unroll
    for (int k = 0; k < K; k++) logit[k] = make_float2(0.f, 0.f);

    for (int c = 0; c < KC; c++) {
        float2 qv = __half22float2(q[(size_t)c * (HW / 2)]);
#pragma unroll
        for (int k = 0; k < K; k++) {
            float kv = kks[c * K + k];
            logit[k].x += qv.x * kv;
            logit[k].y += qv.y * kv;
        }
    }

    float mx = -1e30f, my = -1e30f;
#pragma unroll
    for (int k = 0; k < K; k++) {
        mx = fmaxf(mx, logit[k].x); my = fmaxf(my, logit[k].y);
    }
    float sx = 0.f, sy = 0.f;
#pragma unroll
    for (int k = 0; k < K; k++) {
        logit[k].x = __expf(logit[k].x - mx); sx += logit[k].x;
        logit[k].y = __expf(logit[k].y - my); sy += logit[k].y;
    }
    const float ix = 1.0f / sx, iy = 1.0f / sy;
#pragma unroll
    for (int k = 0; k < K; k++) { logit[k].x *= ix; logit[k].y *= iy; }

    __half2* ctx = (__half2*)(g_ctxh + (size_t)n * KC * HW) + s2;
    for (int c = 0; c < KC; c++) {
        float ax = 0.f, ay = 0.f;
#pragma unroll
        for (int k = 0; k < K; k++) {
            float vv = vls[c * K + k];
            ax += logit[k].x * vv;
            ay += logit[k].y * vv;
        }
        ctx[(size_t)c * (HW / 2)] = __floats2half2_rn(ax, ay);
    }
}

// ---------------- launch ----------------
extern "C" void kernel_launch(void* const* d_in, const int* in_sizes, int n_in,
                              void* d_out, int out_size) {
    (void)in_sizes; (void)n_in; (void)out_size;
    const float* feats = (const float*)d_in[0];
    const float* probs = (const float*)d_in[1];
    const float* wp1 = (const float*)d_in[2];
    const float* bp1 = (const float*)d_in[3];
    const float* sp1 = (const float*)d_in[4];
    const float* tp1 = (const float*)d_in[5];
    const float* wp2 = (const float*)d_in[6];
    const float* bp2 = (const float*)d_in[7];
    const float* sp2 = (const float*)d_in[8];
    const float* tp2 = (const float*)d_in[9];
    const float* wo1 = (const float*)d_in[10];
    const float* bo1 = (const float*)d_in[11];
    const float* so1 = (const float*)d_in[12];
    const float* to1 = (const float*)d_in[13];
    const float* wo2 = (const float*)d_in[14];
    const float* bo2 = (const float*)d_in[15];
    const float* so2 = (const float*)d_in[16];
    const float* to2 = (const float*)d_in[17];
    const float* wd  = (const float*)d_in[18];
    const float* bd  = (const float*)d_in[19];
    const float* sd  = (const float*)d_in[20];
    const float* td  = (const float*)d_in[21];
    const float* wu  = (const float*)d_in[22];
    const float* bu  = (const float*)d_in[23];
    const float* su  = (const float*)d_in[24];
    const float* tu  = (const float*)d_in[25];
    const float* wf  = (const float*)d_in[26];
    const float* bf  = (const float*)d_in[27];
    const float* sf  = (const float*)d_in[28];
    const float* tf  = (const float*)d_in[29];
    float* out = (float*)d_out;

    void *p_proxy, *p_o1, *p_kk, *p_val;
    void *p_featsh, *p_q1h, *p_q2h, *p_ctxh, *p_ctxuph;
    void *p_wp1h, *p_wp2h, *p_wuh, *p_wfh;
    cudaGetSymbolAddress(&p_proxy, g_proxy);
    cudaGetSymbolAddress(&p_o1, g_o1);
    cudaGetSymbolAddress(&p_kk, g_kk);
    cudaGetSymbolAddress(&p_val, g_val);
    cudaGetSymbolAddress(&p_featsh, g_featsh);
    cudaGetSymbolAddress(&p_q1h, g_q1h);
    cudaGetSymbolAddress(&p_q2h, g_q2h);
    cudaGetSymbolAddress(&p_ctxh, g_ctxh);
    cudaGetSymbolAddress(&p_ctxuph, g_ctxuph);
    cudaGetSymbolAddress(&p_wp1h, g_wp1h);
    cudaGetSymbolAddress(&p_wp2h, g_wp2h);
    cudaGetSymbolAddress(&p_wuh, g_wuh);
    cudaGetSymbolAddress(&p_wfh, g_wfh);

    cudaFuncSetAttribute(cbr_gemm_mma, cudaFuncAttributeMaxDynamicSharedMemorySize, GEMM_SMEM);
    cudaFuncSetAttribute(small_cbr2, cudaFuncAttributeMaxDynamicSharedMemorySize, C * 20 * 4);

    static cudaStream_t s2 = nullptr;
    static cudaEvent_t ev_fork = nullptr, ev_feats = nullptr, ev_chainB = nullptr;
    if (s2 == nullptr) {
        cudaStreamCreateWithFlags(&s2, cudaStreamNonBlocking);
        cudaEventCreateWithFlags(&ev_fork, cudaEventDisableTiming);
        cudaEventCreateWithFlags(&ev_feats, cudaEventDisableTiming);
        cudaEventCreateWithFlags(&ev_chainB, cudaEventDisableTiming);
    }

    // ---- fork: chain B (softmax) starts immediately on s2 ----
    cudaEventRecord(ev_fork, 0);
    cudaStreamWaitEvent(s2, ev_fork, 0);
    softmax_kernel<<<NB * K, 512, 0, s2>>>(probs);

    // ---- chain A on stream 0: feats f2h -> weights f2h -> GEMM1 -> GEMM2 ----
    {
        int n4 = NB * C * HW / 4;
        f2h_kernel<<<(n4 + 255) / 256, 256>>>((const float4*)feats, (uint2*)p_featsh, n4);
    }
    cudaEventRecord(ev_feats, 0);
    {
        W4 w;
        w.in[0] = (const float4*)wp1; w.out[0] = (uint2*)p_wp1h;
        w.in[1] = (const float4*)wp2; w.out[1] = (uint2*)p_wp2h;
        w.in[2] = (const float4*)wu;  w.out[2] = (uint2*)p_wuh;
        w.in[3] = (const float4*)wf;  w.out[3] = (uint2*)p_wfh;
        int a = KC * C / 4, b = a + KC * KC / 4, c = b + C * KC / 4, d = c + OUTC * 2 * C / 4;
        w.end[0] = a; w.end[1] = b; w.end[2] = c; w.end[3] = d;
        f2h_weights<<<(d + 255) / 256, 256>>>(w);
    }
    cbr_gemm_mma<<<dim3(KC / 128, HW / 128, NB), 256, GEMM_SMEM>>>(
        (const __half*)p_featsh, nullptr, (const __half*)p_wp1h, bp1, sp1, tp1,
        p_q1h, 1, C, C, KC);
    cbr_gemm_mma<<<dim3(KC / 128, HW / 128, NB), 256, GEMM_SMEM>>>(
        (const __half*)p_q1h, nullptr, (const __half*)p_wp2h, bp2, sp2, tp2,
        p_q2h, 1, KC, KC, KC);

    // ---- chain B on s2: proxy -> reduce -> small_cbrs ----
    cudaStreamWaitEvent(s2, ev_feats, 0);
    proxy_partial2<<<dim3(PCH, NB), 256, 0, s2>>>();
    proxy_reduce<<<(NB * C * K + 255) / 256, 256, 0, s2>>>();
    small_cbr2<<<dim3(NB, 8, 2), 256, C * 20 * 4, s2>>>((const float*)p_proxy,
                                                        wo1, bo1, so1, to1, (float*)p_o1,
                                                        wd, bd, sd, td, (float*)p_val, C, 1.0f);
    small_cbr2<<<dim3(NB, 8, 1), 256, KC * 20 * 4, s2>>>((const float*)p_o1,
                                                         wo2, bo2, so2, to2, (float*)p_kk,
                                                         nullptr, nullptr, nullptr, nullptr, nullptr,
                                                         KC, 0.0625f);
    cudaEventRecord(ev_chainB, s2);

    // ---- join, then attn -> GEMM up -> final GEMM on stream 0 ----
    cudaStreamWaitEvent(0, ev_chainB, 0);
    attn_kernel<<<dim3(HW / 256, NB), 128>>>();

    cbr_gemm_mma<<<dim3(C / 128, HW / 128, NB), 256, GEMM_SMEM>>>(
        (const __half*)p_ctxh, nullptr, (const __half*)p_wuh, bu, su, tu,
        p_ctxuph, 1, KC, KC, C);

    cbr_gemm_mma<<<dim3(OUTC / 128, HW / 128, NB), 256, GEMM_SMEM>>>(
        (const __half*)p_ctxuph, (const __half*)p_featsh, (const __half*)p_wfh, bf, sf, tf,
        out, 0, 2 * C, C, OUTC);
}

// round 16
// speedup vs baseline: 2.8012x; 1.1333x over previous
#include <cuda_runtime.h>
#include <cuda_fp16.h>
#include <cstdint>
#include <math.h>

// Problem constants
static constexpr int NB   = 4;
static constexpr int C    = 512;
static constexpr int HW   = 16384;
static constexpr int K    = 19;
static constexpr int KC   = 256;
static constexpr int OUTC = 512;
static constexpr int PCH  = 128;    // proxy spatial chunks

// ---------------- scratch (device globals, no allocation) ----------------
__device__ float g_p[NB * K * HW];
__device__ float g_ppart[PCH * NB * C * K];
__device__ float g_proxy[NB * C * K];
__device__ float g_o1[NB * KC * K];
__device__ float g_kk[NB * KC * K];
__device__ float g_val[NB * KC * K];
__device__ __half g_featsh[NB * C * HW];
__device__ __half g_q1h[NB * KC * HW];
__device__ __half g_q2h[NB * KC * HW];
__device__ __half g_ctxh[NB * KC * HW];
__device__ __half g_ctxuph[NB * C * HW];
__device__ __half g_wp1h[KC * C];
__device__ __half g_wp2h[KC * KC];
__device__ __half g_wuh[C * KC];
__device__ __half g_wfh[OUTC * 2 * C];

// ---------------- PTX helpers ----------------
__device__ __forceinline__ void mma_f16(float* d, uint32_t a0, uint32_t a1, uint32_t a2, uint32_t a3,
                                        uint32_t b0, uint32_t b1) {
    asm volatile(
        "mma.sync.aligned.m16n8k16.row.col.f32.f16.f16.f32 "
        "{%0,%1,%2,%3}, {%4,%5,%6,%7}, {%8,%9}, {%0,%1,%2,%3};\n"
        : "+f"(d[0]), "+f"(d[1]), "+f"(d[2]), "+f"(d[3])
        : "r"(a0), "r"(a1), "r"(a2), "r"(a3), "r"(b0), "r"(b1));
}
__device__ __forceinline__ void ldm_x4(uint32_t* r, uint32_t addr) {
    asm volatile("ldmatrix.sync.aligned.m8n8.x4.shared.b16 {%0,%1,%2,%3}, [%4];"
                 : "=r"(r[0]), "=r"(r[1]), "=r"(r[2]), "=r"(r[3]) : "r"(addr));
}
__device__ __forceinline__ void ldm_x4_t(uint32_t* r, uint32_t addr) {
    asm volatile("ldmatrix.sync.aligned.m8n8.x4.trans.shared.b16 {%0,%1,%2,%3}, [%4];"
                 : "=r"(r[0]), "=r"(r[1]), "=r"(r[2]), "=r"(r[3]) : "r"(addr));
}
__device__ __forceinline__ void cp16(uint32_t saddr, const void* g) {
    asm volatile("cp.async.cg.shared.global [%0], [%1], 16;" :: "r"(saddr), "l"(g) : "memory");
}
__device__ __forceinline__ void cp_commit() { asm volatile("cp.async.commit_group;" ::: "memory"); }
template <int N>
__device__ __forceinline__ void cp_wait() { asm volatile("cp.async.wait_group %0;" :: "n"(N) : "memory"); }

// ---------------- 0) fp32 -> fp16 conversions ----------------
__global__ __launch_bounds__(256) void f2h_kernel(const float4* __restrict__ in,
                                                  uint2* __restrict__ out, int n4) {
    int i = blockIdx.x * 256 + threadIdx.x;
    if (i >= n4) return;
    float4 v = in[i];
    __half2 a = __floats2half2_rn(v.x, v.y);
    __half2 b = __floats2half2_rn(v.z, v.w);
    uint2 t; t.x = *(uint32_t*)&a; t.y = *(uint32_t*)&b;
    out[i] = t;
}

struct W4 {
    const float4* in[4];
    uint2* out[4];
    int end[4];
};
__global__ __launch_bounds__(256) void f2h_weights(W4 w) {
    int i = blockIdx.x * 256 + threadIdx.x;
    int r = 0, base = 0;
    if (i >= w.end[3]) return;
    if (i >= w.end[2])      { r = 3; base = w.end[2]; }
    else if (i >= w.end[1]) { r = 2; base = w.end[1]; }
    else if (i >= w.end[0]) { r = 1; base = w.end[0]; }
    int j = i - base;
    float4 v = w.in[r][j];
    __half2 a = __floats2half2_rn(v.x, v.y);
    __half2 b = __floats2half2_rn(v.z, v.w);
    uint2 t; t.x = *(uint32_t*)&a; t.y = *(uint32_t*)&b;
    w.out[r][j] = t;
}

// ---------------- 1) spatial softmax over probs ----------------
__global__ __launch_bounds__(512) void softmax_kernel(const float* __restrict__ probs) {
    const int row = blockIdx.x;
    const float4* x4 = (const float4*)(probs + (size_t)row * HW);
    float4* y4 = (float4*)(g_p + (size_t)row * HW);
    const int tid = threadIdx.x;
    const int lane = tid & 31, wrp = tid >> 5;
    __shared__ float red[16];

    float m = -1e30f;
    for (int i = tid; i < HW / 4; i += 512) {
        float4 v = x4[i];
        m = fmaxf(fmaxf(m, fmaxf(v.x, v.y)), fmaxf(v.z, v.w));
    }
#pragma unroll
    for (int off = 16; off > 0; off >>= 1) m = fmaxf(m, __shfl_xor_sync(~0u, m, off));
    if (lane == 0) red[wrp] = m;
    __syncthreads();
    m = red[lane & 15];
#pragma unroll
    for (int off = 8; off > 0; off >>= 1) m = fmaxf(m, __shfl_xor_sync(~0u, m, off));

    float sum = 0.f;
    for (int i = tid; i < HW / 4; i += 512) {
        float4 v = x4[i];
        v.x = __expf(v.x - m); v.y = __expf(v.y - m);
        v.z = __expf(v.z - m); v.w = __expf(v.w - m);
        y4[i] = v;
        sum += v.x + v.y + v.z + v.w;
    }
#pragma unroll
    for (int off = 16; off > 0; off >>= 1) sum += __shfl_xor_sync(~0u, sum, off);
    __syncthreads();
    if (lane == 0) red[wrp] = sum;
    __syncthreads();
    sum = red[lane & 15];
#pragma unroll
    for (int off = 8; off > 0; off >>= 1) sum += __shfl_xor_sync(~0u, sum, off);
    const float inv = 1.0f / sum;
    for (int i = tid; i < HW / 4; i += 512) {
        float4 v = y4[i];
        v.x *= inv; v.y *= inv; v.z *= inv; v.w *= inv;
        y4[i] = v;
    }
}

// ---------------- 2) proxy pooling: transposed smem tile ----------------
__global__ __launch_bounds__(256) void proxy_partial2() {
    const int ch = blockIdx.x;
    const int n  = blockIdx.y;
    const int tid = threadIdx.x;

    __shared__ __half sf[32][520];
    __shared__ float sp[19][33];

    float acc[2][K];
#pragma unroll
    for (int h = 0; h < 2; h++)
#pragma unroll
        for (int k = 0; k < K; k++) acc[h][k] = 0.f;

    const __half* fb = g_featsh + (size_t)n * C * HW;
    const float* pb = g_p + (size_t)n * K * HW;
    const int c0 = 2 * tid;
    const int sbeg = ch * (HW / PCH), send = sbeg + (HW / PCH);

    for (int s0 = sbeg; s0 < send; s0 += 32) {
        {
            int c = tid;
#pragma unroll
            for (int h = 0; h < 2; h++, c += 256) {
                const __half* gp = fb + (size_t)c * HW + s0;
#pragma unroll
                for (int q = 0; q < 4; q++) {
                    uint4 v = *(const uint4*)(gp + q * 8);
                    const __half* hh = (const __half*)&v;
#pragma unroll
                    for (int j = 0; j < 8; j++) sf[q * 8 + j][c] = hh[j];
                }
            }
        }
        for (int i = tid; i < K * 32; i += 256) {
            int k = i >> 5, s = i & 31;
            sp[k][s] = pb[(size_t)k * HW + s0 + s];
        }
        __syncthreads();
#pragma unroll 2
        for (int s = 0; s < 32; s++) {
            __half2 hv = *(const __half2*)&sf[s][c0];
            float2 f = __half22float2(hv);
#pragma unroll
            for (int k = 0; k < K; k++) {
                float pv = sp[k][s];
                acc[0][k] += f.x * pv;
                acc[1][k] += f.y * pv;
            }
        }
        __syncthreads();
    }

#pragma unroll
    for (int h = 0; h < 2; h++) {
        float* ob = g_ppart + ((size_t)ch * NB + n) * C * K + (size_t)(c0 + h) * K;
#pragma unroll
        for (int k = 0; k < K; k++) ob[k] = acc[h][k];
    }
}

__global__ __launch_bounds__(256) void proxy_reduce() {
    int e = blockIdx.x * 256 + threadIdx.x;
    if (e >= NB * C * K) return;
    float s = 0.f;
#pragma unroll 8
    for (int ch = 0; ch < PCH; ch++) s += g_ppart[(size_t)ch * NB * C * K + e];
    g_proxy[e] = s;
}

// ---------------- 3) tiny conv1x1+BN+ReLU ----------------
__global__ __launch_bounds__(256) void small_cbr2(const float* __restrict__ in,
                                                  const float* __restrict__ wA,
                                                  const float* __restrict__ bA,
                                                  const float* __restrict__ scA,
                                                  const float* __restrict__ shA,
                                                  float* __restrict__ outA,
                                                  const float* __restrict__ wB,
                                                  const float* __restrict__ bB,
                                                  const float* __restrict__ scB,
                                                  const float* __restrict__ shB,
                                                  float* __restrict__ outB,
                                                  int Cin, float fscale) {
    const int n = blockIdx.x;
    const int ob = blockIdx.y;
    const int tid = threadIdx.x;
    const float* w  = blockIdx.z ? wB : wA;
    const float* b  = blockIdx.z ? bB : bA;
    const float* sc = blockIdx.z ? scB : scA;
    const float* sh = blockIdx.z ? shB : shA;
    float* out      = blockIdx.z ? outB : outA;

    extern __shared__ float sin_[];
    const float* ibase = in + (size_t)n * Cin * K;
    for (int i = tid; i < Cin * 20; i += 256) {
        int c = i / 20, k = i - c * 20;
        sin_[i] = (k < K) ? ibase[c * K + k] : 0.f;
    }
    __syncthreads();

    const int o = ob * 32 + (tid >> 3);
    const int part = tid & 7;

    float acc[K];
#pragma unroll
    for (int k = 0; k < K; k++) acc[k] = 0.f;

    const float* wrow = w + (size_t)o * Cin;
    for (int c = part; c < Cin; c += 8) {
        float wv = wrow[c];
        const float* srow = &sin_[c * 20];
#pragma unroll
        for (int k = 0; k < K; k++) acc[k] += wv * srow[k];
    }
#pragma unroll
    for (int off = 4; off > 0; off >>= 1)
#pragma unroll
        for (int k = 0; k < K; k++) acc[k] += __shfl_down_sync(0xffffffffu, acc[k], off, 8);

    if (part == 0) {
        const float bb = b[o], ss = sc[o], tt = sh[o];
        float* obase = out + ((size_t)n * KC + o) * K;
#pragma unroll
        for (int k = 0; k < K; k++) obase[k] = fmaxf((acc[k] + bb) * ss + tt, 0.f) * fscale;
    }
}

// ---------------- 4) fp16 mma + cp.async(4-stage) + ldmatrix CBR GEMM (R12 config) ----------------
static constexpr int A_PITCH_H = 40;
static constexpr int B_PITCH_H = 136;
static constexpr int A_BYTES = 128 * A_PITCH_H * 2;
static constexpr int B_BYTES = 32 * B_PITCH_H * 2;
static constexpr int NSTAGE = 4;
static constexpr int GEMM_SMEM = NSTAGE * (A_BYTES + B_BYTES) + 3 * 128 * 4;

__global__ __launch_bounds__(256) void cbr_gemm_mma(const __half* __restrict__ in1,
                                                    const __half* __restrict__ in2,
                                                    const __half* __restrict__ wh,
                                                    const float* __restrict__ bias,
                                                    const float* __restrict__ sc,
                                                    const float* __restrict__ sh,
                                                    void* __restrict__ outp, int out_half,
                                                    int Cin, int split, int Cout) {
    extern __shared__ char smem_c[];
    float* par = (float*)(smem_c + NSTAGE * (A_BYTES + B_BYTES));

    const int tid  = threadIdx.x;
    const int lane = tid & 31;
    const int wid  = tid >> 5;
    const int n    = blockIdx.z;
    const int s0   = blockIdx.x * 128;
    const int o0   = blockIdx.y * 128;

    const int m0w = (wid & 1) * 64;
    const int n0w = (wid >> 1) * 32;
    const int gid = lane >> 2;
    const int tg  = lane & 3;

    uint32_t smem_u32;
    asm("{ .reg .u64 t; cvta.to.shared.u64 t, %1; cvt.u32.u64 %0, t; }" : "=r"(smem_u32) : "l"(smem_c));
    const uint32_t A_u = smem_u32;
    const uint32_t B_u = smem_u32 + NSTAGE * A_BYTES;

    if (tid < 128) {
        par[tid]       = bias[o0 + tid];
        par[128 + tid] = sc[o0 + tid];
        par[256 + tid] = sh[o0 + tid];
    }

    const int T = Cin >> 5;
    const __half* in1n = in1 + (size_t)n * split * HW;
    const __half* in2n = in2 ? (in2 + (size_t)n * (Cin - split) * HW) : nullptr;

    const int bkk = tid >> 4, bcq = tid & 15;
    const int am  = tid >> 2, acq = tid & 3;

    float acc[4][4][4];
#pragma unroll
    for (int mi = 0; mi < 4; mi++)
#pragma unroll
        for (int ni = 0; ni < 4; ni++)
#pragma unroll
            for (int r = 0; r < 4; r++) acc[mi][ni][r] = 0.f;

    auto load_tile = [&](int kt) {
        const int st = kt & (NSTAGE - 1);
        const uint32_t Ab = A_u + st * A_BYTES;
        const uint32_t Bb = B_u + st * B_BYTES;
        const int k0 = kt << 5;
        const __half* src; int krel;
        if (k0 < split) { src = in1n; krel = k0; } else { src = in2n; krel = k0 - split; }
        cp16(Bb + (bkk * B_PITCH_H + bcq * 8) * 2,
             src + (size_t)(krel + bkk) * HW + s0 + bcq * 8);
        cp16(Bb + ((bkk + 16) * B_PITCH_H + bcq * 8) * 2,
             src + (size_t)(krel + bkk + 16) * HW + s0 + bcq * 8);
        cp16(Ab + (am * A_PITCH_H + acq * 8) * 2,
             wh + (size_t)(o0 + am) * Cin + k0 + acq * 8);
        cp16(Ab + ((am + 64) * A_PITCH_H + acq * 8) * 2,
             wh + (size_t)(o0 + am + 64) * Cin + k0 + acq * 8);
        cp_commit();
    };

    const uint32_t a_off = ((lane & 15) * A_PITCH_H + (lane >> 4) * 8) * 2;
    const uint32_t b_off = ((lane & 15) * B_PITCH_H + n0w + (lane >> 4) * 8) * 2;

    load_tile(0);
    load_tile(1);
    load_tile(2);

    for (int kt = 0; kt < T; kt++) {
        if (kt + 1 >= T)      { cp_wait<0>(); }
        else if (kt + 2 >= T) { cp_wait<1>(); }
        else                  { cp_wait<2>(); }
        __syncthreads();
        if (kt + 3 < T) load_tile(kt + 3);

        const int st = kt & (NSTAGE - 1);
        const uint32_t Ab = A_u + st * A_BYTES;
        const uint32_t Bb = B_u + st * B_BYTES;
#pragma unroll
        for (int ks = 0; ks < 2; ks++) {
            const int k16 = ks * 16;
            uint32_t af[4][4], bf[4][2];
#pragma unroll
            for (int mi = 0; mi < 4; mi++)
                ldm_x4(af[mi], Ab + a_off + ((m0w + mi * 16) * A_PITCH_H + k16) * 2);
#pragma unroll
            for (int np = 0; np < 2; np++) {
                uint32_t r[4];
                ldm_x4_t(r, Bb + b_off + (k16 * B_PITCH_H + np * 16) * 2);
                bf[np * 2][0] = r[0]; bf[np * 2][1] = r[1];
                bf[np * 2 + 1][0] = r[2]; bf[np * 2 + 1][1] = r[3];
            }
#pragma unroll
            for (int mi = 0; mi < 4; mi++)
#pragma unroll
                for (int ni = 0; ni < 4; ni++)
                    mma_f16(acc[mi][ni], af[mi][0], af[mi][1], af[mi][2], af[mi][3],
                            bf[ni][0], bf[ni][1]);
        }
    }

    // epilogue
#pragma unroll
    for (int mi = 0; mi < 4; mi++) {
        int r  = m0w + mi * 16 + gid;
        float b_lo = par[r], s_lo = par[128 + r], t_lo = par[256 + r];
        float b_hi = par[r + 8], s_hi = par[128 + r + 8], t_hi = par[256 + r + 8];
        if (out_half) {
            __half* outn = (__half*)outp + (size_t)n * Cout * HW;
            __half* row_lo = outn + (size_t)(o0 + r) * HW + s0;
            __half* row_hi = outn + (size_t)(o0 + r + 8) * HW + s0;
#pragma unroll
            for (int ni = 0; ni < 4; ni++) {
                int cc = n0w + ni * 8 + tg * 2;
                float lx = fmaxf((acc[mi][ni][0] + b_lo) * s_lo + t_lo, 0.f);
                float ly = fmaxf((acc[mi][ni][1] + b_lo) * s_lo + t_lo, 0.f);
                float hx = fmaxf((acc[mi][ni][2] + b_hi) * s_hi + t_hi, 0.f);
                float hy = fmaxf((acc[mi][ni][3] + b_hi) * s_hi + t_hi, 0.f);
                *(__half2*)&row_lo[cc] = __floats2half2_rn(lx, ly);
                *(__half2*)&row_hi[cc] = __floats2half2_rn(hx, hy);
            }
        } else {
            float* outn = (float*)outp + (size_t)n * Cout * HW;
            float* row_lo = outn + (size_t)(o0 + r) * HW + s0;
            float* row_hi = outn + (size_t)(o0 + r + 8) * HW + s0;
#pragma unroll
            for (int ni = 0; ni < 4; ni++) {
                int cc = n0w + ni * 8 + tg * 2;
                float2 lo, hi;
                lo.x = fmaxf((acc[mi][ni][0] + b_lo) * s_lo + t_lo, 0.f);
                lo.y = fmaxf((acc[mi][ni][1] + b_lo) * s_lo + t_lo, 0.f);
                hi.x = fmaxf((acc[mi][ni][2] + b_hi) * s_hi + t_hi, 0.f);
                hi.y = fmaxf((acc[mi][ni][3] + b_hi) * s_hi + t_hi, 0.f);
                *(float2*)&row_lo[cc] = lo;
                *(float2*)&row_hi[cc] = hi;
            }
        }
    }
}

// ---------------- 5) fused attention: 8-way channel split per pixel-pair ----------------
// 256 threads: lane = g*4-ish mapping -> pp = lane & 3 (pixel pair), g = lane >> 2 (c-group).
// Each thread: partial logits over 32 channels (c = g + 8i), shfl-xor reduce over g,
// redundant softmax, then ctx for its 32-channel slice.
static constexpr int TP = 264;   // transposed smem pitch (floats)

__global__ __launch_bounds__(256) void attn_kernel2() {
    const int n = blockIdx.y;
    const int tid = threadIdx.x;
    const int lane = tid & 31, w = tid >> 5;
    const int pp = lane & 3, g = lane >> 2;
    const int s2 = blockIdx.x * 32 + w * 4 + pp;   // pixel-pair index

    __shared__ float kks[K * TP];
    __shared__ float vls[K * TP];
    const float* kkb = g_kk + (size_t)n * KC * K;
    const float* vlb = g_val + (size_t)n * KC * K;
    for (int i = tid; i < KC * K; i += 256) {
        int c = i / K, k = i - c * K;
        kks[k * TP + c] = kkb[i];
        vls[k * TP + c] = vlb[i];
    }
    __syncthreads();

    const __half2* q = (const __half2*)(g_q2h + (size_t)n * KC * HW) + s2;
    float2 logit[K];
#pragma unroll
    for (int k = 0; k < K; k++) logit[k] = make_float2(0.f, 0.f);

#pragma unroll 4
    for (int i = 0; i < 32; i++) {
        int c = g + 8 * i;
        float2 qv = __half22float2(q[(size_t)c * (HW / 2)]);
#pragma unroll
        for (int k = 0; k < K; k++) {
            float kv = kks[k * TP + c];
            logit[k].x += qv.x * kv;
            logit[k].y += qv.y * kv;
        }
    }

    // reduce partial logits over the 8 c-groups (lanes differing in g)
#pragma unroll
    for (int off = 4; off <= 16; off <<= 1)
#pragma unroll
        for (int k = 0; k < K; k++) {
            logit[k].x += __shfl_xor_sync(0xffffffffu, logit[k].x, off);
            logit[k].y += __shfl_xor_sync(0xffffffffu, logit[k].y, off);
        }

    // softmax (kk already folded with 1/sqrt(KC))
    float mx = -1e30f, my = -1e30f;
#pragma unroll
    for (int k = 0; k < K; k++) {
        mx = fmaxf(mx, logit[k].x); my = fmaxf(my, logit[k].y);
    }
    float sx = 0.f, sy = 0.f;
#pragma unroll
    for (int k = 0; k < K; k++) {
        logit[k].x = __expf(logit[k].x - mx); sx += logit[k].x;
        logit[k].y = __expf(logit[k].y - my); sy += logit[k].y;
    }
    const float ix = 1.0f / sx, iy = 1.0f / sy;
#pragma unroll
    for (int k = 0; k < K; k++) { logit[k].x *= ix; logit[k].y *= iy; }

    __half2* ctx = (__half2*)(g_ctxh + (size_t)n * KC * HW) + s2;
#pragma unroll 4
    for (int i = 0; i < 32; i++) {
        int c = g + 8 * i;
        float ax = 0.f, ay = 0.f;
#pragma unroll
        for (int k = 0; k < K; k++) {
            float vv = vls[k * TP + c];
            ax += logit[k].x * vv;
            ay += logit[k].y * vv;
        }
        ctx[(size_t)c * (HW / 2)] = __floats2half2_rn(ax, ay);
    }
}

// ---------------- launch ----------------
extern "C" void kernel_launch(void* const* d_in, const int* in_sizes, int n_in,
                              void* d_out, int out_size) {
    (void)in_sizes; (void)n_in; (void)out_size;
    const float* feats = (const float*)d_in[0];
    const float* probs = (const float*)d_in[1];
    const float* wp1 = (const float*)d_in[2];
    const float* bp1 = (const float*)d_in[3];
    const float* sp1 = (const float*)d_in[4];
    const float* tp1 = (const float*)d_in[5];
    const float* wp2 = (const float*)d_in[6];
    const float* bp2 = (const float*)d_in[7];
    const float* sp2 = (const float*)d_in[8];
    const float* tp2 = (const float*)d_in[9];
    const float* wo1 = (const float*)d_in[10];
    const float* bo1 = (const float*)d_in[11];
    const float* so1 = (const float*)d_in[12];
    const float* to1 = (const float*)d_in[13];
    const float* wo2 = (const float*)d_in[14];
    const float* bo2 = (const float*)d_in[15];
    const float* so2 = (const float*)d_in[16];
    const float* to2 = (const float*)d_in[17];
    const float* wd  = (const float*)d_in[18];
    const float* bd  = (const float*)d_in[19];
    const float* sd  = (const float*)d_in[20];
    const float* td  = (const float*)d_in[21];
    const float* wu  = (const float*)d_in[22];
    const float* bu  = (const float*)d_in[23];
    const float* su  = (const float*)d_in[24];
    const float* tu  = (const float*)d_in[25];
    const float* wf  = (const float*)d_in[26];
    const float* bf  = (const float*)d_in[27];
    const float* sf  = (const float*)d_in[28];
    const float* tf  = (const float*)d_in[29];
    float* out = (float*)d_out;

    void *p_proxy, *p_o1, *p_kk, *p_val;
    void *p_featsh, *p_q1h, *p_q2h, *p_ctxh, *p_ctxuph;
    void *p_wp1h, *p_wp2h, *p_wuh, *p_wfh;
    cudaGetSymbolAddress(&p_proxy, g_proxy);
    cudaGetSymbolAddress(&p_o1, g_o1);
    cudaGetSymbolAddress(&p_kk, g_kk);
    cudaGetSymbolAddress(&p_val, g_val);
    cudaGetSymbolAddress(&p_featsh, g_featsh);
    cudaGetSymbolAddress(&p_q1h, g_q1h);
    cudaGetSymbolAddress(&p_q2h, g_q2h);
    cudaGetSymbolAddress(&p_ctxh, g_ctxh);
    cudaGetSymbolAddress(&p_ctxuph, g_ctxuph);
    cudaGetSymbolAddress(&p_wp1h, g_wp1h);
    cudaGetSymbolAddress(&p_wp2h, g_wp2h);
    cudaGetSymbolAddress(&p_wuh, g_wuh);
    cudaGetSymbolAddress(&p_wfh, g_wfh);

    cudaFuncSetAttribute(cbr_gemm_mma, cudaFuncAttributeMaxDynamicSharedMemorySize, GEMM_SMEM);
    cudaFuncSetAttribute(small_cbr2, cudaFuncAttributeMaxDynamicSharedMemorySize, C * 20 * 4);

    static cudaStream_t s2 = nullptr;
    static cudaEvent_t ev_fork = nullptr, ev_feats = nullptr, ev_chainB = nullptr;
    if (s2 == nullptr) {
        cudaStreamCreateWithFlags(&s2, cudaStreamNonBlocking);
        cudaEventCreateWithFlags(&ev_fork, cudaEventDisableTiming);
        cudaEventCreateWithFlags(&ev_feats, cudaEventDisableTiming);
        cudaEventCreateWithFlags(&ev_chainB, cudaEventDisableTiming);
    }

    // ---- fork: chain B (softmax) starts immediately on s2 ----
    cudaEventRecord(ev_fork, 0);
    cudaStreamWaitEvent(s2, ev_fork, 0);
    softmax_kernel<<<NB * K, 512, 0, s2>>>(probs);

    // ---- chain A on stream 0: feats f2h -> weights f2h -> GEMM1 -> GEMM2 ----
    {
        int n4 = NB * C * HW / 4;
        f2h_kernel<<<(n4 + 255) / 256, 256>>>((const float4*)feats, (uint2*)p_featsh, n4);
    }
    cudaEventRecord(ev_feats, 0);
    {
        W4 w;
        w.in[0] = (const float4*)wp1; w.out[0] = (uint2*)p_wp1h;
        w.in[1] = (const float4*)wp2; w.out[1] = (uint2*)p_wp2h;
        w.in[2] = (const float4*)wu;  w.out[2] = (uint2*)p_wuh;
        w.in[3] = (const float4*)wf;  w.out[3] = (uint2*)p_wfh;
        int a = KC * C / 4, b = a + KC * KC / 4, c = b + C * KC / 4, d = c + OUTC * 2 * C / 4;
        w.end[0] = a; w.end[1] = b; w.end[2] = c; w.end[3] = d;
        f2h_weights<<<(d + 255) / 256, 256>>>(w);
    }
    cbr_gemm_mma<<<dim3(HW / 128, KC / 128, NB), 256, GEMM_SMEM>>>(
        (const __half*)p_featsh, nullptr, (const __half*)p_wp1h, bp1, sp1, tp1,
        p_q1h, 1, C, C, KC);
    cbr_gemm_mma<<<dim3(HW / 128, KC / 128, NB), 256, GEMM_SMEM>>>(
        (const __half*)p_q1h, nullptr, (const __half*)p_wp2h, bp2, sp2, tp2,
        p_q2h, 1, KC, KC, KC);

    // ---- chain B on s2: proxy -> reduce -> small_cbrs ----
    cudaStreamWaitEvent(s2, ev_feats, 0);
    proxy_partial2<<<dim3(PCH, NB), 256, 0, s2>>>();
    proxy_reduce<<<(NB * C * K + 255) / 256, 256, 0, s2>>>();
    small_cbr2<<<dim3(NB, 8, 2), 256, C * 20 * 4, s2>>>((const float*)p_proxy,
                                                        wo1, bo1, so1, to1, (float*)p_o1,
                                                        wd, bd, sd, td, (float*)p_val, C, 1.0f);
    small_cbr2<<<dim3(NB, 8, 1), 256, KC * 20 * 4, s2>>>((const float*)p_o1,
                                                         wo2, bo2, so2, to2, (float*)p_kk,
                                                         nullptr, nullptr, nullptr, nullptr, nullptr,
                                                         KC, 0.0625f);
    cudaEventRecord(ev_chainB, s2);

    // ---- join, then attn -> GEMM up -> final GEMM on stream 0 ----
    cudaStreamWaitEvent(0, ev_chainB, 0);
    attn_kernel2<<<dim3(HW / 64, NB), 256>>>();

    cbr_gemm_mma<<<dim3(HW / 128, C / 128, NB), 256, GEMM_SMEM>>>(
        (const __half*)p_ctxh, nullptr, (const __half*)p_wuh, bu, su, tu,
        p_ctxuph, 1, KC, KC, C);

    cbr_gemm_mma<<<dim3(HW / 128, OUTC / 128, NB), 256, GEMM_SMEM>>>(
        (const __half*)p_ctxuph, (const __half*)p_featsh, (const __half*)p_wfh, bf, sf, tf,
        out, 0, 2 * C, C, OUTC);
}

// round 17
// speedup vs baseline: 2.8167x; 1.0055x over previous
#include <cuda_runtime.h>
#include <cuda_fp16.h>
#include <cstdint>
#include <math.h>

// Problem constants
static constexpr int NB   = 4;
static constexpr int C    = 512;
static constexpr int HW   = 16384;
static constexpr int K    = 19;
static constexpr int KC   = 256;
static constexpr int OUTC = 512;
static constexpr int PCH  = 128;    // proxy spatial chunks

// ---------------- scratch (device globals, no allocation) ----------------
__device__ float g_p[NB * K * HW];
__device__ float g_ppart[PCH * NB * C * K];
__device__ float g_proxy[NB * C * K];
__device__ float g_o1[NB * KC * K];
__device__ float g_kk[NB * KC * K];
__device__ float g_val[NB * KC * K];
__device__ __half g_featsh[NB * C * HW];
__device__ __half g_q1h[NB * KC * HW];
__device__ __half g_q2h[NB * KC * HW];
__device__ __half g_ctxh[NB * KC * HW];
__device__ __half g_ctxuph[NB * C * HW];
__device__ __half g_wp1h[KC * C];
__device__ __half g_wp2h[KC * KC];
__device__ __half g_wuh[C * KC];
__device__ __half g_wfh[OUTC * 2 * C];

// ---------------- PTX helpers ----------------
__device__ __forceinline__ void mma_f16(float* d, uint32_t a0, uint32_t a1, uint32_t a2, uint32_t a3,
                                        uint32_t b0, uint32_t b1) {
    asm volatile(
        "mma.sync.aligned.m16n8k16.row.col.f32.f16.f16.f32 "
        "{%0,%1,%2,%3}, {%4,%5,%6,%7}, {%8,%9}, {%0,%1,%2,%3};\n"
        : "+f"(d[0]), "+f"(d[1]), "+f"(d[2]), "+f"(d[3])
        : "r"(a0), "r"(a1), "r"(a2), "r"(a3), "r"(b0), "r"(b1));
}
__device__ __forceinline__ void ldm_x4(uint32_t* r, uint32_t addr) {
    asm volatile("ldmatrix.sync.aligned.m8n8.x4.shared.b16 {%0,%1,%2,%3}, [%4];"
                 : "=r"(r[0]), "=r"(r[1]), "=r"(r[2]), "=r"(r[3]) : "r"(addr));
}
__device__ __forceinline__ void ldm_x4_t(uint32_t* r, uint32_t addr) {
    asm volatile("ldmatrix.sync.aligned.m8n8.x4.trans.shared.b16 {%0,%1,%2,%3}, [%4];"
                 : "=r"(r[0]), "=r"(r[1]), "=r"(r[2]), "=r"(r[3]) : "r"(addr));
}
__device__ __forceinline__ void cp16(uint32_t saddr, const void* g) {
    asm volatile("cp.async.cg.shared.global [%0], [%1], 16;" :: "r"(saddr), "l"(g) : "memory");
}
__device__ __forceinline__ void cp_commit() { asm volatile("cp.async.commit_group;" ::: "memory"); }
template <int N>
__device__ __forceinline__ void cp_wait() { asm volatile("cp.async.wait_group %0;" :: "n"(N) : "memory"); }

// ---------------- 0) fp32 -> fp16 conversions ----------------
__global__ __launch_bounds__(256) void f2h_kernel(const float4* __restrict__ in,
                                                  uint2* __restrict__ out, int n4) {
    int i = blockIdx.x * 256 + threadIdx.x;
    if (i >= n4) return;
    float4 v = in[i];
    __half2 a = __floats2half2_rn(v.x, v.y);
    __half2 b = __floats2half2_rn(v.z, v.w);
    uint2 t; t.x = *(uint32_t*)&a; t.y = *(uint32_t*)&b;
    out[i] = t;
}

struct W4 {
    const float4* in[4];
    uint2* out[4];
    int end[4];
};
__global__ __launch_bounds__(256) void f2h_weights(W4 w) {
    int i = blockIdx.x * 256 + threadIdx.x;
    int r = 0, base = 0;
    if (i >= w.end[3]) return;
    if (i >= w.end[2])      { r = 3; base = w.end[2]; }
    else if (i >= w.end[1]) { r = 2; base = w.end[1]; }
    else if (i >= w.end[0]) { r = 1; base = w.end[0]; }
    int j = i - base;
    float4 v = w.in[r][j];
    __half2 a = __floats2half2_rn(v.x, v.y);
    __half2 b = __floats2half2_rn(v.z, v.w);
    uint2 t; t.x = *(uint32_t*)&a; t.y = *(uint32_t*)&b;
    w.out[r][j] = t;
}

// ---------------- 1) spatial softmax over probs ----------------
__global__ __launch_bounds__(512) void softmax_kernel(const float* __restrict__ probs) {
    const int row = blockIdx.x;
    const float4* x4 = (const float4*)(probs + (size_t)row * HW);
    float4* y4 = (float4*)(g_p + (size_t)row * HW);
    const int tid = threadIdx.x;
    const int lane = tid & 31, wrp = tid >> 5;
    __shared__ float red[16];

    float m = -1e30f;
    for (int i = tid; i < HW / 4; i += 512) {
        float4 v = x4[i];
        m = fmaxf(fmaxf(m, fmaxf(v.x, v.y)), fmaxf(v.z, v.w));
    }
#pragma unroll
    for (int off = 16; off > 0; off >>= 1) m = fmaxf(m, __shfl_xor_sync(~0u, m, off));
    if (lane == 0) red[wrp] = m;
    __syncthreads();
    m = red[lane & 15];
#pragma unroll
    for (int off = 8; off > 0; off >>= 1) m = fmaxf(m, __shfl_xor_sync(~0u, m, off));

    float sum = 0.f;
    for (int i = tid; i < HW / 4; i += 512) {
        float4 v = x4[i];
        v.x = __expf(v.x - m); v.y = __expf(v.y - m);
        v.z = __expf(v.z - m); v.w = __expf(v.w - m);
        y4[i] = v;
        sum += v.x + v.y + v.z + v.w;
    }
#pragma unroll
    for (int off = 16; off > 0; off >>= 1) sum += __shfl_xor_sync(~0u, sum, off);
    __syncthreads();
    if (lane == 0) red[wrp] = sum;
    __syncthreads();
    sum = red[lane & 15];
#pragma unroll
    for (int off = 8; off > 0; off >>= 1) sum += __shfl_xor_sync(~0u, sum, off);
    const float inv = 1.0f / sum;
    for (int i = tid; i < HW / 4; i += 512) {
        float4 v = y4[i];
        v.x *= inv; v.y *= inv; v.z *= inv; v.w *= inv;
        y4[i] = v;
    }
}

// ---------------- 2) proxy pooling: transposed smem tile ----------------
__global__ __launch_bounds__(256) void proxy_partial2() {
    const int ch = blockIdx.x;
    const int n  = blockIdx.y;
    const int tid = threadIdx.x;

    __shared__ __half sf[32][520];
    __shared__ float sp[19][33];

    float acc[2][K];
#pragma unroll
    for (int h = 0; h < 2; h++)
#pragma unroll
        for (int k = 0; k < K; k++) acc[h][k] = 0.f;

    const __half* fb = g_featsh + (size_t)n * C * HW;
    const float* pb = g_p + (size_t)n * K * HW;
    const int c0 = 2 * tid;
    const int sbeg = ch * (HW / PCH), send = sbeg + (HW / PCH);

    for (int s0 = sbeg; s0 < send; s0 += 32) {
        {
            int c = tid;
#pragma unroll
            for (int h = 0; h < 2; h++, c += 256) {
                const __half* gp = fb + (size_t)c * HW + s0;
#pragma unroll
                for (int q = 0; q < 4; q++) {
                    uint4 v = *(const uint4*)(gp + q * 8);
                    const __half* hh = (const __half*)&v;
#pragma unroll
                    for (int j = 0; j < 8; j++) sf[q * 8 + j][c] = hh[j];
                }
            }
        }
        for (int i = tid; i < K * 32; i += 256) {
            int k = i >> 5, s = i & 31;
            sp[k][s] = pb[(size_t)k * HW + s0 + s];
        }
        __syncthreads();
#pragma unroll 2
        for (int s = 0; s < 32; s++) {
            __half2 hv = *(const __half2*)&sf[s][c0];
            float2 f = __half22float2(hv);
#pragma unroll
            for (int k = 0; k < K; k++) {
                float pv = sp[k][s];
                acc[0][k] += f.x * pv;
                acc[1][k] += f.y * pv;
            }
        }
        __syncthreads();
    }

#pragma unroll
    for (int h = 0; h < 2; h++) {
        float* ob = g_ppart + ((size_t)ch * NB + n) * C * K + (size_t)(c0 + h) * K;
#pragma unroll
        for (int k = 0; k < K; k++) ob[k] = acc[h][k];
    }
}

__global__ __launch_bounds__(256) void proxy_reduce() {
    int e = blockIdx.x * 256 + threadIdx.x;
    if (e >= NB * C * K) return;
    float s = 0.f;
#pragma unroll 8
    for (int ch = 0; ch < PCH; ch++) s += g_ppart[(size_t)ch * NB * C * K + e];
    g_proxy[e] = s;
}

// ---------------- 3) tiny conv1x1+BN+ReLU ----------------
__global__ __launch_bounds__(256) void small_cbr2(const float* __restrict__ in,
                                                  const float* __restrict__ wA,
                                                  const float* __restrict__ bA,
                                                  const float* __restrict__ scA,
                                                  const float* __restrict__ shA,
                                                  float* __restrict__ outA,
                                                  const float* __restrict__ wB,
                                                  const float* __restrict__ bB,
                                                  const float* __restrict__ scB,
                                                  const float* __restrict__ shB,
                                                  float* __restrict__ outB,
                                                  int Cin, float fscale) {
    const int n = blockIdx.x;
    const int ob = blockIdx.y;
    const int tid = threadIdx.x;
    const float* w  = blockIdx.z ? wB : wA;
    const float* b  = blockIdx.z ? bB : bA;
    const float* sc = blockIdx.z ? scB : scA;
    const float* sh = blockIdx.z ? shB : shA;
    float* out      = blockIdx.z ? outB : outA;

    extern __shared__ float sin_[];
    const float* ibase = in + (size_t)n * Cin * K;
    for (int i = tid; i < Cin * 20; i += 256) {
        int c = i / 20, k = i - c * 20;
        sin_[i] = (k < K) ? ibase[c * K + k] : 0.f;
    }
    __syncthreads();

    const int o = ob * 32 + (tid >> 3);
    const int part = tid & 7;

    float acc[K];
#pragma unroll
    for (int k = 0; k < K; k++) acc[k] = 0.f;

    const float* wrow = w + (size_t)o * Cin;
    for (int c = part; c < Cin; c += 8) {
        float wv = wrow[c];
        const float* srow = &sin_[c * 20];
#pragma unroll
        for (int k = 0; k < K; k++) acc[k] += wv * srow[k];
    }
#pragma unroll
    for (int off = 4; off > 0; off >>= 1)
#pragma unroll
        for (int k = 0; k < K; k++) acc[k] += __shfl_down_sync(0xffffffffu, acc[k], off, 8);

    if (part == 0) {
        const float bb = b[o], ss = sc[o], tt = sh[o];
        float* obase = out + ((size_t)n * KC + o) * K;
#pragma unroll
        for (int k = 0; k < K; k++) obase[k] = fmaxf((acc[k] + bb) * ss + tt, 0.f) * fscale;
    }
}

// ---------------- 4) fp16 mma + cp.async(4-stage) + ldmatrix CBR GEMM (R12 config) ----------------
static constexpr int A_PITCH_H = 40;
static constexpr int B_PITCH_H = 136;
static constexpr int A_BYTES = 128 * A_PITCH_H * 2;
static constexpr int B_BYTES = 32 * B_PITCH_H * 2;
static constexpr int NSTAGE = 4;
static constexpr int GEMM_SMEM = NSTAGE * (A_BYTES + B_BYTES) + 3 * 128 * 4;

__global__ __launch_bounds__(256) void cbr_gemm_mma(const __half* __restrict__ in1,
                                                    const __half* __restrict__ in2,
                                                    const __half* __restrict__ wh,
                                                    const float* __restrict__ bias,
                                                    const float* __restrict__ sc,
                                                    const float* __restrict__ sh,
                                                    void* __restrict__ outp, int out_half,
                                                    int Cin, int split, int Cout) {
    extern __shared__ char smem_c[];
    float* par = (float*)(smem_c + NSTAGE * (A_BYTES + B_BYTES));

    const int tid  = threadIdx.x;
    const int lane = tid & 31;
    const int wid  = tid >> 5;
    const int n    = blockIdx.z;
    const int s0   = blockIdx.x * 128;
    const int o0   = blockIdx.y * 128;

    const int m0w = (wid & 1) * 64;
    const int n0w = (wid >> 1) * 32;
    const int gid = lane >> 2;
    const int tg  = lane & 3;

    uint32_t smem_u32;
    asm("{ .reg .u64 t; cvta.to.shared.u64 t, %1; cvt.u32.u64 %0, t; }" : "=r"(smem_u32) : "l"(smem_c));
    const uint32_t A_u = smem_u32;
    const uint32_t B_u = smem_u32 + NSTAGE * A_BYTES;

    if (tid < 128) {
        par[tid]       = bias[o0 + tid];
        par[128 + tid] = sc[o0 + tid];
        par[256 + tid] = sh[o0 + tid];
    }

    const int T = Cin >> 5;
    const __half* in1n = in1 + (size_t)n * split * HW;
    const __half* in2n = in2 ? (in2 + (size_t)n * (Cin - split) * HW) : nullptr;

    const int bkk = tid >> 4, bcq = tid & 15;
    const int am  = tid >> 2, acq = tid & 3;

    float acc[4][4][4];
#pragma unroll
    for (int mi = 0; mi < 4; mi++)
#pragma unroll
        for (int ni = 0; ni < 4; ni++)
#pragma unroll
            for (int r = 0; r < 4; r++) acc[mi][ni][r] = 0.f;

    auto load_tile = [&](int kt) {
        const int st = kt & (NSTAGE - 1);
        const uint32_t Ab = A_u + st * A_BYTES;
        const uint32_t Bb = B_u + st * B_BYTES;
        const int k0 = kt << 5;
        const __half* src; int krel;
        if (k0 < split) { src = in1n; krel = k0; } else { src = in2n; krel = k0 - split; }
        cp16(Bb + (bkk * B_PITCH_H + bcq * 8) * 2,
             src + (size_t)(krel + bkk) * HW + s0 + bcq * 8);
        cp16(Bb + ((bkk + 16) * B_PITCH_H + bcq * 8) * 2,
             src + (size_t)(krel + bkk + 16) * HW + s0 + bcq * 8);
        cp16(Ab + (am * A_PITCH_H + acq * 8) * 2,
             wh + (size_t)(o0 + am) * Cin + k0 + acq * 8);
        cp16(Ab + ((am + 64) * A_PITCH_H + acq * 8) * 2,
             wh + (size_t)(o0 + am + 64) * Cin + k0 + acq * 8);
        cp_commit();
    };

    const uint32_t a_off = ((lane & 15) * A_PITCH_H + (lane >> 4) * 8) * 2;
    const uint32_t b_off = ((lane & 15) * B_PITCH_H + n0w + (lane >> 4) * 8) * 2;

    load_tile(0);
    load_tile(1);
    load_tile(2);

    for (int kt = 0; kt < T; kt++) {
        if (kt + 1 >= T)      { cp_wait<0>(); }
        else if (kt + 2 >= T) { cp_wait<1>(); }
        else                  { cp_wait<2>(); }
        __syncthreads();
        if (kt + 3 < T) load_tile(kt + 3);

        const int st = kt & (NSTAGE - 1);
        const uint32_t Ab = A_u + st * A_BYTES;
        const uint32_t Bb = B_u + st * B_BYTES;
#pragma unroll
        for (int ks = 0; ks < 2; ks++) {
            const int k16 = ks * 16;
            uint32_t af[4][4], bf[4][2];
#pragma unroll
            for (int mi = 0; mi < 4; mi++)
                ldm_x4(af[mi], Ab + a_off + ((m0w + mi * 16) * A_PITCH_H + k16) * 2);
#pragma unroll
            for (int np = 0; np < 2; np++) {
                uint32_t r[4];
                ldm_x4_t(r, Bb + b_off + (k16 * B_PITCH_H + np * 16) * 2);
                bf[np * 2][0] = r[0]; bf[np * 2][1] = r[1];
                bf[np * 2 + 1][0] = r[2]; bf[np * 2 + 1][1] = r[3];
            }
#pragma unroll
            for (int mi = 0; mi < 4; mi++)
#pragma unroll
                for (int ni = 0; ni < 4; ni++)
                    mma_f16(acc[mi][ni], af[mi][0], af[mi][1], af[mi][2], af[mi][3],
                            bf[ni][0], bf[ni][1]);
        }
    }

    // epilogue
#pragma unroll
    for (int mi = 0; mi < 4; mi++) {
        int r  = m0w + mi * 16 + gid;
        float b_lo = par[r], s_lo = par[128 + r], t_lo = par[256 + r];
        float b_hi = par[r + 8], s_hi = par[128 + r + 8], t_hi = par[256 + r + 8];
        if (out_half) {
            __half* outn = (__half*)outp + (size_t)n * Cout * HW;
            __half* row_lo = outn + (size_t)(o0 + r) * HW + s0;
            __half* row_hi = outn + (size_t)(o0 + r + 8) * HW + s0;
#pragma unroll
            for (int ni = 0; ni < 4; ni++) {
                int cc = n0w + ni * 8 + tg * 2;
                float lx = fmaxf((acc[mi][ni][0] + b_lo) * s_lo + t_lo, 0.f);
                float ly = fmaxf((acc[mi][ni][1] + b_lo) * s_lo + t_lo, 0.f);
                float hx = fmaxf((acc[mi][ni][2] + b_hi) * s_hi + t_hi, 0.f);
                float hy = fmaxf((acc[mi][ni][3] + b_hi) * s_hi + t_hi, 0.f);
                *(__half2*)&row_lo[cc] = __floats2half2_rn(lx, ly);
                *(__half2*)&row_hi[cc] = __floats2half2_rn(hx, hy);
            }
        } else {
            float* outn = (float*)outp + (size_t)n * Cout * HW;
            float* row_lo = outn + (size_t)(o0 + r) * HW + s0;
            float* row_hi = outn + (size_t)(o0 + r + 8) * HW + s0;
#pragma unroll
            for (int ni = 0; ni < 4; ni++) {
                int cc = n0w + ni * 8 + tg * 2;
                float2 lo, hi;
                lo.x = fmaxf((acc[mi][ni][0] + b_lo) * s_lo + t_lo, 0.f);
                lo.y = fmaxf((acc[mi][ni][1] + b_lo) * s_lo + t_lo, 0.f);
                hi.x = fmaxf((acc[mi][ni][2] + b_hi) * s_hi + t_hi, 0.f);
                hi.y = fmaxf((acc[mi][ni][3] + b_hi) * s_hi + t_hi, 0.f);
                *(float2*)&row_lo[cc] = lo;
                *(float2*)&row_hi[cc] = hi;
            }
        }
    }
}

// ---------------- 5) fused attention: 8-way channel split per pixel-pair ----------------
static constexpr int TP = 264;   // transposed smem pitch (floats)

__global__ __launch_bounds__(256) void attn_kernel2() {
    const int n = blockIdx.y;
    const int tid = threadIdx.x;
    const int lane = tid & 31, w = tid >> 5;
    const int pp = lane & 3, g = lane >> 2;
    const int s2 = blockIdx.x * 32 + w * 4 + pp;   // pixel-pair index

    __shared__ float kks[K * TP];
    __shared__ float vls[K * TP];
    const float* kkb = g_kk + (size_t)n * KC * K;
    const float* vlb = g_val + (size_t)n * KC * K;
    for (int i = tid; i < KC * K; i += 256) {
        int c = i / K, k = i - c * K;
        kks[k * TP + c] = kkb[i];
        vls[k * TP + c] = vlb[i];
    }
    __syncthreads();

    const __half2* q = (const __half2*)(g_q2h + (size_t)n * KC * HW) + s2;
    float2 logit[K];
#pragma unroll
    for (int k = 0; k < K; k++) logit[k] = make_float2(0.f, 0.f);

#pragma unroll 4
    for (int i = 0; i < 32; i++) {
        int c = g + 8 * i;
        float2 qv = __half22float2(q[(size_t)c * (HW / 2)]);
#pragma unroll
        for (int k = 0; k < K; k++) {
            float kv = kks[k * TP + c];
            logit[k].x += qv.x * kv;
            logit[k].y += qv.y * kv;
        }
    }

#pragma unroll
    for (int off = 4; off <= 16; off <<= 1)
#pragma unroll
        for (int k = 0; k < K; k++) {
            logit[k].x += __shfl_xor_sync(0xffffffffu, logit[k].x, off);
            logit[k].y += __shfl_xor_sync(0xffffffffu, logit[k].y, off);
        }

    float mx = -1e30f, my = -1e30f;
#pragma unroll
    for (int k = 0; k < K; k++) {
        mx = fmaxf(mx, logit[k].x); my = fmaxf(my, logit[k].y);
    }
    float sx = 0.f, sy = 0.f;
#pragma unroll
    for (int k = 0; k < K; k++) {
        logit[k].x = __expf(logit[k].x - mx); sx += logit[k].x;
        logit[k].y = __expf(logit[k].y - my); sy += logit[k].y;
    }
    const float ix = 1.0f / sx, iy = 1.0f / sy;
#pragma unroll
    for (int k = 0; k < K; k++) { logit[k].x *= ix; logit[k].y *= iy; }

    __half2* ctx = (__half2*)(g_ctxh + (size_t)n * KC * HW) + s2;
#pragma unroll 4
    for (int i = 0; i < 32; i++) {
        int c = g + 8 * i;
        float ax = 0.f, ay = 0.f;
#pragma unroll
        for (int k = 0; k < K; k++) {
            float vv = vls[k * TP + c];
            ax += logit[k].x * vv;
            ay += logit[k].y * vv;
        }
        ctx[(size_t)c * (HW / 2)] = __floats2half2_rn(ax, ay);
    }
}

// ---------------- launch ----------------
extern "C" void kernel_launch(void* const* d_in, const int* in_sizes, int n_in,
                              void* d_out, int out_size) {
    (void)in_sizes; (void)n_in; (void)out_size;
    const float* feats = (const float*)d_in[0];
    const float* probs = (const float*)d_in[1];
    const float* wp1 = (const float*)d_in[2];
    const float* bp1 = (const float*)d_in[3];
    const float* sp1 = (const float*)d_in[4];
    const float* tp1 = (const float*)d_in[5];
    const float* wp2 = (const float*)d_in[6];
    const float* bp2 = (const float*)d_in[7];
    const float* sp2 = (const float*)d_in[8];
    const float* tp2 = (const float*)d_in[9];
    const float* wo1 = (const float*)d_in[10];
    const float* bo1 = (const float*)d_in[11];
    const float* so1 = (const float*)d_in[12];
    const float* to1 = (const float*)d_in[13];
    const float* wo2 = (const float*)d_in[14];
    const float* bo2 = (const float*)d_in[15];
    const float* so2 = (const float*)d_in[16];
    const float* to2 = (const float*)d_in[17];
    const float* wd  = (const float*)d_in[18];
    const float* bd  = (const float*)d_in[19];
    const float* sd  = (const float*)d_in[20];
    const float* td  = (const float*)d_in[21];
    const float* wu  = (const float*)d_in[22];
    const float* bu  = (const float*)d_in[23];
    const float* su  = (const float*)d_in[24];
    const float* tu  = (const float*)d_in[25];
    const float* wf  = (const float*)d_in[26];
    const float* bf  = (const float*)d_in[27];
    const float* sf  = (const float*)d_in[28];
    const float* tf  = (const float*)d_in[29];
    float* out = (float*)d_out;

    void *p_proxy, *p_o1, *p_kk, *p_val;
    void *p_featsh, *p_q1h, *p_q2h, *p_ctxh, *p_ctxuph;
    void *p_wp1h, *p_wp2h, *p_wuh, *p_wfh;
    cudaGetSymbolAddress(&p_proxy, g_proxy);
    cudaGetSymbolAddress(&p_o1, g_o1);
    cudaGetSymbolAddress(&p_kk, g_kk);
    cudaGetSymbolAddress(&p_val, g_val);
    cudaGetSymbolAddress(&p_featsh, g_featsh);
    cudaGetSymbolAddress(&p_q1h, g_q1h);
    cudaGetSymbolAddress(&p_q2h, g_q2h);
    cudaGetSymbolAddress(&p_ctxh, g_ctxh);
    cudaGetSymbolAddress(&p_ctxuph, g_ctxuph);
    cudaGetSymbolAddress(&p_wp1h, g_wp1h);
    cudaGetSymbolAddress(&p_wp2h, g_wp2h);
    cudaGetSymbolAddress(&p_wuh, g_wuh);
    cudaGetSymbolAddress(&p_wfh, g_wfh);

    cudaFuncSetAttribute(cbr_gemm_mma, cudaFuncAttributeMaxDynamicSharedMemorySize, GEMM_SMEM);
    cudaFuncSetAttribute(small_cbr2, cudaFuncAttributeMaxDynamicSharedMemorySize, C * 20 * 4);

    static cudaStream_t s2 = nullptr, s3 = nullptr;
    static cudaEvent_t ev_fork = nullptr, ev_w = nullptr, ev_fA = nullptr, ev_fB = nullptr,
                       ev_chainB = nullptr, ev_g = nullptr;
    if (s2 == nullptr) {
        cudaStreamCreateWithFlags(&s2, cudaStreamNonBlocking);
        cudaStreamCreateWithFlags(&s3, cudaStreamNonBlocking);
        cudaEventCreateWithFlags(&ev_fork, cudaEventDisableTiming);
        cudaEventCreateWithFlags(&ev_w, cudaEventDisableTiming);
        cudaEventCreateWithFlags(&ev_fA, cudaEventDisableTiming);
        cudaEventCreateWithFlags(&ev_fB, cudaEventDisableTiming);
        cudaEventCreateWithFlags(&ev_chainB, cudaEventDisableTiming);
        cudaEventCreateWithFlags(&ev_g, cudaEventDisableTiming);
    }

    const int half4 = NB * C * HW / 8;   // float4 count per 2 batches

    // ---- fork ----
    cudaEventRecord(ev_fork, 0);
    cudaStreamWaitEvent(s2, ev_fork, 0);
    cudaStreamWaitEvent(s3, ev_fork, 0);

    // s2: weight f2h first (GEMM1 dependency), then softmax
    {
        W4 w;
        w.in[0] = (const float4*)wp1; w.out[0] = (uint2*)p_wp1h;
        w.in[1] = (const float4*)wp2; w.out[1] = (uint2*)p_wp2h;
        w.in[2] = (const float4*)wu;  w.out[2] = (uint2*)p_wuh;
        w.in[3] = (const float4*)wf;  w.out[3] = (uint2*)p_wfh;
        int a = KC * C / 4, b = a + KC * KC / 4, c = b + C * KC / 4, d = c + OUTC * 2 * C / 4;
        w.end[0] = a; w.end[1] = b; w.end[2] = c; w.end[3] = d;
        f2h_weights<<<(d + 255) / 256, 256, 0, s2>>>(w);
    }
    cudaEventRecord(ev_w, s2);
    softmax_kernel<<<NB * K, 512, 0, s2>>>(probs);

    // stream 0: feats f2h in two halves (batches 0-1, then 2-3)
    f2h_kernel<<<(half4 + 255) / 256, 256>>>((const float4*)feats, (uint2*)p_featsh, half4);
    cudaEventRecord(ev_fA, 0);
    f2h_kernel<<<(half4 + 255) / 256, 256>>>((const float4*)feats + half4,
                                             (uint2*)p_featsh + half4, half4);
    cudaEventRecord(ev_fB, 0);

    // s3: GEMM1 (first half overlaps second f2h half), then GEMM1 half 2, then GEMM2
    cudaStreamWaitEvent(s3, ev_w, 0);
    cudaStreamWaitEvent(s3, ev_fA, 0);
    cbr_gemm_mma<<<dim3(HW / 128, KC / 128, 2), 256, GEMM_SMEM, s3>>>(
        (const __half*)p_featsh, nullptr, (const __half*)p_wp1h, bp1, sp1, tp1,
        p_q1h, 1, C, C, KC);
    cudaStreamWaitEvent(s3, ev_fB, 0);
    cbr_gemm_mma<<<dim3(HW / 128, KC / 128, 2), 256, GEMM_SMEM, s3>>>(
        (const __half*)p_featsh + (size_t)2 * C * HW, nullptr, (const __half*)p_wp1h, bp1, sp1, tp1,
        (__half*)p_q1h + (size_t)2 * KC * HW, 1, C, C, KC);
    cbr_gemm_mma<<<dim3(HW / 128, KC / 128, NB), 256, GEMM_SMEM, s3>>>(
        (const __half*)p_q1h, nullptr, (const __half*)p_wp2h, bp2, sp2, tp2,
        p_q2h, 1, KC, KC, KC);
    cudaEventRecord(ev_g, s3);

    // s2 (chain B): proxy (needs full featsh) -> reduce -> small_cbrs
    cudaStreamWaitEvent(s2, ev_fB, 0);
    proxy_partial2<<<dim3(PCH, NB), 256, 0, s2>>>();
    proxy_reduce<<<(NB * C * K + 255) / 256, 256, 0, s2>>>();
    small_cbr2<<<dim3(NB, 8, 2), 256, C * 20 * 4, s2>>>((const float*)p_proxy,
                                                        wo1, bo1, so1, to1, (float*)p_o1,
                                                        wd, bd, sd, td, (float*)p_val, C, 1.0f);
    small_cbr2<<<dim3(NB, 8, 1), 256, KC * 20 * 4, s2>>>((const float*)p_o1,
                                                         wo2, bo2, so2, to2, (float*)p_kk,
                                                         nullptr, nullptr, nullptr, nullptr, nullptr,
                                                         KC, 0.0625f);
    cudaEventRecord(ev_chainB, s2);

    // ---- join on stream 0: attn -> GEMM up -> final GEMM ----
    cudaStreamWaitEvent(0, ev_g, 0);
    cudaStreamWaitEvent(0, ev_chainB, 0);
    attn_kernel2<<<dim3(HW / 64, NB), 256>>>();

    cbr_gemm_mma<<<dim3(HW / 128, C / 128, NB), 256, GEMM_SMEM>>>(
        (const __half*)p_ctxh, nullptr, (const __half*)p_wuh, bu, su, tu,
        p_ctxuph, 1, KC, KC, C);

    cbr_gemm_mma<<<dim3(HW / 128, OUTC / 128, NB), 256, GEMM_SMEM>>>(
        (const __half*)p_ctxuph, (const __half*)p_featsh, (const __half*)p_wfh, bf, sf, tf,
        out, 0, 2 * C, C, OUTC);
}